// round 1
// baseline (speedup 1.0000x reference)
#include <cuda_runtime.h>

// Problem constants
#define BSZ   2048
#define K1    9408     // 3*56*56
#define N1    1024     // PROJ_OUT
#define HD    2048     // HIDDEN_DIM
#define NC    65       // N_CLASSES
#define WLD   3072     // W_fc leading dim (HD + N1)

// Deterministic scratch (no atomics anywhere)
__device__ float g_partial[16 * N1];        // per-M-block column sums of relu(z2p)
__device__ float g_u[N1];                   // column sums of z2p
__device__ float g_T[NC];                   // S2[c] + 2048*b_fc[c]
__device__ float g_s1part[8 * BSZ * NC];    // split-K partials of s1

// ---------------------------------------------------------------------------
// GEMM1: per-tile relu(z2f @ Wp^T + bias), reduced to column partial sums.
// A = z2f [2048,9408] row-major, B = W_proj [1024,9408] row-major (both K-major).
// BM=128, BN=64, BK=16, 256 threads, 8x4 register tile. Register-prefetched.
// ---------------------------------------------------------------------------
__global__ __launch_bounds__(256, 2) void gemm1_kernel(
    const float* __restrict__ A, const float* __restrict__ B,
    const float* __restrict__ bias)
{
    __shared__ float As[16][132];   // [k][m], padded
    __shared__ float Bs[16][68];    // [k][n], padded
    __shared__ float red[16][64];

    const int tid  = threadIdx.x;
    const int tx   = tid & 15;      // 16 col-groups * 4 cols
    const int ty   = tid >> 4;      // 16 row-groups * 8 rows
    const int row0 = blockIdx.y * 128;
    const int col0 = blockIdx.x * 64;

    const int lrow = tid >> 2;      // 0..63
    const int lq   = tid & 3;       // float4 index within BK=16

    const float* Aptr0 = A + (size_t)(row0 + lrow) * K1 + lq * 4;
    const float* Aptr1 = Aptr0 + (size_t)64 * K1;
    const float* Bptr  = B + (size_t)(col0 + lrow) * K1 + lq * 4;

    float acc[8][4];
    #pragma unroll
    for (int r = 0; r < 8; r++)
        #pragma unroll
        for (int c = 0; c < 4; c++) acc[r][c] = 0.f;

    // prefetch first tiles into registers
    float4 pa0 = *(const float4*)(Aptr0);
    float4 pa1 = *(const float4*)(Aptr1);
    float4 pb  = *(const float4*)(Bptr);

    for (int k0 = 0; k0 < K1; k0 += 16) {
        __syncthreads();
        As[lq*4+0][lrow]    = pa0.x; As[lq*4+1][lrow]    = pa0.y;
        As[lq*4+2][lrow]    = pa0.z; As[lq*4+3][lrow]    = pa0.w;
        As[lq*4+0][lrow+64] = pa1.x; As[lq*4+1][lrow+64] = pa1.y;
        As[lq*4+2][lrow+64] = pa1.z; As[lq*4+3][lrow+64] = pa1.w;
        Bs[lq*4+0][lrow]    = pb.x;  Bs[lq*4+1][lrow]    = pb.y;
        Bs[lq*4+2][lrow]    = pb.z;  Bs[lq*4+3][lrow]    = pb.w;
        __syncthreads();

        if (k0 + 16 < K1) {   // prefetch next tile (overlaps compute)
            pa0 = *(const float4*)(Aptr0 + k0 + 16);
            pa1 = *(const float4*)(Aptr1 + k0 + 16);
            pb  = *(const float4*)(Bptr  + k0 + 16);
        }

        #pragma unroll
        for (int k = 0; k < 16; k++) {
            float4 av0 = *(const float4*)(&As[k][ty*8]);
            float4 av1 = *(const float4*)(&As[k][ty*8+4]);
            float4 bv  = *(const float4*)(&Bs[k][tx*4]);
            float a[8] = {av0.x,av0.y,av0.z,av0.w,av1.x,av1.y,av1.z,av1.w};
            float b[4] = {bv.x,bv.y,bv.z,bv.w};
            #pragma unroll
            for (int r = 0; r < 8; r++)
                #pragma unroll
                for (int c = 0; c < 4; c++)
                    acc[r][c] += a[r] * b[c];
        }
    }

    // Epilogue: bias + relu, sum columns over this block's 128 rows.
    float csum[4];
    #pragma unroll
    for (int c = 0; c < 4; c++) {
        float bb = bias[col0 + tx*4 + c];
        float s = 0.f;
        #pragma unroll
        for (int r = 0; r < 8; r++)
            s += fmaxf(acc[r][c] + bb, 0.f);
        csum[c] = s;
    }
    __syncthreads();
    #pragma unroll
    for (int c = 0; c < 4; c++) red[ty][tx*4+c] = csum[c];
    __syncthreads();
    if (tid < 64) {
        float s = 0.f;
        #pragma unroll
        for (int i = 0; i < 16; i++) s += red[i][tid];
        g_partial[blockIdx.y * N1 + col0 + tid] = s;
    }
}

// u[j] = sum over 16 M-blocks of partial column sums
__global__ void reduce_u_kernel()
{
    int j = blockIdx.x * 256 + threadIdx.x;
    if (j < N1) {
        float s = 0.f;
        #pragma unroll
        for (int m = 0; m < 16; m++) s += g_partial[m * N1 + j];
        g_u[j] = s;
    }
}

// g_T[c] = u . W_fc[c, HD:] + 2048*b_fc[c]
__global__ void s2_kernel(const float* __restrict__ Wfc, const float* __restrict__ bfc)
{
    __shared__ float red[128];
    const int c = blockIdx.x, tid = threadIdx.x;
    const float* w = Wfc + (size_t)c * WLD + HD;
    float p = 0.f;
    for (int k = tid; k < N1; k += 128) p += g_u[k] * w[k];
    red[tid] = p;
    __syncthreads();
    for (int s = 64; s > 0; s >>= 1) {
        if (tid < s) red[tid] += red[tid + s];
        __syncthreads();
    }
    if (tid == 0) g_T[c] = red[0] + 2048.f * bfc[c];
}

// ---------------------------------------------------------------------------
// s1 = z1 @ W_fc[:, :HD]^T, split-K: grid (16 M-tiles, 8 K-slices of 256).
// BM=128, BK=16. Thread: 8 rows x 5 cols (13 of 16 col-groups active).
// ---------------------------------------------------------------------------
__global__ __launch_bounds__(256, 2) void s1_kernel(
    const float* __restrict__ A, const float* __restrict__ W)
{
    __shared__ float As[16][132];
    __shared__ float Bs[16][68];

    const int tid   = threadIdx.x;
    const int cg    = tid & 15;   // 5 cols each; active if cg < 13
    const int rg    = tid >> 4;   // 8 rows each
    const int row0  = blockIdx.x * 128;
    const int kbase = blockIdx.y * 256;

    const int lrow = tid >> 2;
    const int lq   = tid & 3;
    const float* Aptr0 = A + (size_t)(row0 + lrow) * HD + kbase + lq * 4;
    const float* Aptr1 = Aptr0 + (size_t)64 * HD;

    float acc[8][5];
    #pragma unroll
    for (int r = 0; r < 8; r++)
        #pragma unroll
        for (int j = 0; j < 5; j++) acc[r][j] = 0.f;

    for (int kk = 0; kk < 256; kk += 16) {
        __syncthreads();
        {
            float4 a0 = *(const float4*)(Aptr0 + kk);
            float4 a1 = *(const float4*)(Aptr1 + kk);
            As[lq*4+0][lrow]    = a0.x; As[lq*4+1][lrow]    = a0.y;
            As[lq*4+2][lrow]    = a0.z; As[lq*4+3][lrow]    = a0.w;
            As[lq*4+0][lrow+64] = a1.x; As[lq*4+1][lrow+64] = a1.y;
            As[lq*4+2][lrow+64] = a1.z; As[lq*4+3][lrow+64] = a1.w;
        }
        for (int f = tid; f < NC * 4; f += 256) {
            int n = f >> 2, q = f & 3;
            float4 w = *(const float4*)(W + (size_t)n * WLD + kbase + kk + q * 4);
            Bs[q*4+0][n] = w.x; Bs[q*4+1][n] = w.y;
            Bs[q*4+2][n] = w.z; Bs[q*4+3][n] = w.w;
        }
        __syncthreads();

        if (cg < 13) {
            #pragma unroll
            for (int k = 0; k < 16; k++) {
                float4 av0 = *(const float4*)(&As[k][rg*8]);
                float4 av1 = *(const float4*)(&As[k][rg*8+4]);
                float a[8] = {av0.x,av0.y,av0.z,av0.w,av1.x,av1.y,av1.z,av1.w};
                #pragma unroll
                for (int j = 0; j < 5; j++) {
                    float b = Bs[k][cg*5 + j];
                    #pragma unroll
                    for (int r = 0; r < 8; r++)
                        acc[r][j] += a[r] * b;
                }
            }
        }
    }

    if (cg < 13) {
        #pragma unroll
        for (int r = 0; r < 8; r++)
            #pragma unroll
            for (int j = 0; j < 5; j++)
                g_s1part[(size_t)blockIdx.y * (BSZ * NC)
                         + (size_t)(row0 + rg*8 + r) * NC + cg*5 + j] = acc[r][j];
    }
}

// out[i,c] = 2048 * s1[i,c] + g_T[c]
__global__ void out_kernel(float* __restrict__ out)
{
    int idx = blockIdx.x * 256 + threadIdx.x;
    if (idx < BSZ * NC) {
        int c = idx % NC;
        float s = 0.f;
        #pragma unroll
        for (int sl = 0; sl < 8; sl++) s += g_s1part[sl * (BSZ * NC) + idx];
        out[idx] = 2048.f * s + g_T[c];
    }
}

extern "C" void kernel_launch(void* const* d_in, const int* in_sizes, int n_in,
                              void* d_out, int out_size)
{
    const float* z1  = (const float*)d_in[0];
    const float* z2  = (const float*)d_in[1];   // [2048,3,56,56] contiguous = [2048,9408]
    const float* Wp  = (const float*)d_in[2];
    const float* bp  = (const float*)d_in[3];
    const float* Wfc = (const float*)d_in[4];
    const float* bfc = (const float*)d_in[5];
    float* out = (float*)d_out;

    gemm1_kernel<<<dim3(16, 16), 256>>>(z2, Wp, bp);
    reduce_u_kernel<<<4, 256>>>();
    s2_kernel<<<NC, 128>>>(Wfc, bfc);
    s1_kernel<<<dim3(16, 8), 256>>>(z1, Wfc);
    out_kernel<<<(BSZ * NC + 255) / 256, 256>>>(out);
}

// round 4
// speedup vs baseline: 4.0035x; 4.0035x over previous
#include <cuda_runtime.h>
#include <cuda_bf16.h>
#include <cstdint>

// Problem constants
#define BSZ   2048
#define K1    9408     // 3*56*56
#define N1    1024     // PROJ_OUT
#define HD    2048     // HIDDEN_DIM
#define NC    65       // N_CLASSES
#define WLD   3072     // W_fc leading dim
#define KSPLIT 16      // s1 split-K slices

// ---------------------------------------------------------------------------
// PTX helpers (baseline ISA only — no 'a'-suffix features)
// ---------------------------------------------------------------------------
__device__ __forceinline__ uint32_t smem_to_u32(const void* p) {
    uint32_t a;
    asm("{ .reg .u64 t; cvta.to.shared.u64 t, %1; cvt.u32.u64 %0, t; }" : "=r"(a) : "l"(p));
    return a;
}
#define CP_ASYNC_16(dst, src) \
    asm volatile("cp.async.cg.shared.global [%0], [%1], 16;" :: "r"(dst), "l"(src))
#define CP_ASYNC_COMMIT() asm volatile("cp.async.commit_group;" ::: "memory")
#define CP_ASYNC_WAIT(n)  asm volatile("cp.async.wait_group %0;" :: "n"(n) : "memory")

#define LDSM_X4(r0,r1,r2,r3,addr) \
    asm volatile("ldmatrix.sync.aligned.m8n8.x4.shared.b16 {%0,%1,%2,%3}, [%4];" \
        : "=r"(r0),"=r"(r1),"=r"(r2),"=r"(r3) : "r"(addr))

#define MMA_BF16(c0,c1,c2,c3,a0,a1,a2,a3,b0,b1) \
    asm volatile("mma.sync.aligned.m16n8k16.row.col.f32.bf16.bf16.f32 " \
        "{%0,%1,%2,%3}, {%4,%5,%6,%7}, {%8,%9}, {%0,%1,%2,%3};" \
        : "+f"(c0),"+f"(c1),"+f"(c2),"+f"(c3) \
        : "r"(a0),"r"(a1),"r"(a2),"r"(a3), "r"(b0),"r"(b1))

// ---------------------------------------------------------------------------
// Scratch
// ---------------------------------------------------------------------------
__device__ __nv_bfloat16 g_Abf[(size_t)BSZ * K1];   // z2f bf16 (38.5 MB)
__device__ __nv_bfloat16 g_Bbf[(size_t)N1 * K1];    // W_proj bf16 (19.3 MB)
__device__ float g_partial[16 * N1];                // per-M-block column sums
__device__ float g_u[N1];
__device__ float g_T[NC];
__device__ float g_s1part[KSPLIT * BSZ * NC];

// ---------------------------------------------------------------------------
// fp32 -> bf16 conversion
// ---------------------------------------------------------------------------
__global__ void convert_kernel(const float* __restrict__ src, __nv_bfloat16* __restrict__ dst, int n4)
{
    int i = blockIdx.x * blockDim.x + threadIdx.x;
    int stride = gridDim.x * blockDim.x;
    for (; i < n4; i += stride) {
        float4 f = ((const float4*)src)[i];
        __nv_bfloat162 lo = __floats2bfloat162_rn(f.x, f.y);
        __nv_bfloat162 hi = __floats2bfloat162_rn(f.z, f.w);
        uint2 v;
        v.x = *(uint32_t*)&lo;
        v.y = *(uint32_t*)&hi;
        ((uint2*)dst)[i] = v;
    }
}

// ---------------------------------------------------------------------------
// GEMM1 via mma.sync bf16: relu(A@B^T + bias) reduced to column sums.
// A[2048,9408] bf16 K-major, B[1024,9408] bf16 K-major.
// CTA tile 128x128, BK=32, 8 warps (2x4), warp tile 64x32, 4-stage cp.async.
// Both A and B are K-major -> NON-trans ldmatrix for both operands.
// ---------------------------------------------------------------------------
#define G1_ITERS   294                 // 9408 / 32
#define ROWB       80                  // smem row stride bytes (32 bf16 + 8 pad)
#define TILE_HALF  (128 * 40)          // halves per tile (A or B)
#define STAGE_B    (2 * TILE_HALF * 2) // bytes per stage (A+B) = 20480
#define NSTAGE     4
#define SRED_OFF   (NSTAGE * STAGE_B)  // 81920
#define G1_SMEM    (SRED_OFF + 8 * 32 * 4)

__global__ __launch_bounds__(256, 1) void gemm1_tc(
    const __nv_bfloat16* __restrict__ Ag, const __nv_bfloat16* __restrict__ Bg,
    const float* __restrict__ bias)
{
    extern __shared__ char smem[];
    const uint32_t sb = smem_to_u32(smem);
    const int tid  = threadIdx.x;
    const int lane = tid & 31;
    const int warp = tid >> 5;
    const int wm   = warp >> 2;        // 0..1  (M 64-half)
    const int wn   = warp & 3;         // 0..3  (N 32-quarter)
    const int mtile = blockIdx.x & 15;
    const int ntile = blockIdx.x >> 4;
    const int row0 = mtile * 128;
    const int col0 = ntile * 128;

    // stage loader: 512 A chunks + 512 B chunks of 16B; 2 (A,B) pairs per thread per i
    auto load_stage = [&](int buf, int k0) {
        const uint32_t sa = sb + buf * STAGE_B;
        const uint32_t sB = sa + TILE_HALF * 2;
        #pragma unroll
        for (int i = 0; i < 2; i++) {
            int v = tid + i * 256;       // 0..511
            int r = v >> 2, c = v & 3;
            CP_ASYNC_16(sa + r * ROWB + c * 16,
                        Ag + (size_t)(row0 + r) * K1 + k0 + c * 8);
            CP_ASYNC_16(sB + r * ROWB + c * 16,
                        Bg + (size_t)(col0 + r) * K1 + k0 + c * 8);
        }
    };

    float acc[4][4][4];
    #pragma unroll
    for (int mt = 0; mt < 4; mt++)
        #pragma unroll
        for (int nt = 0; nt < 4; nt++)
            #pragma unroll
            for (int q = 0; q < 4; q++) acc[mt][nt][q] = 0.f;

    // prefetch 3 stages
    #pragma unroll
    for (int s = 0; s < 3; s++) { load_stage(s, s * 32); CP_ASYNC_COMMIT(); }

    const int lrow = lane & 15;
    const int lseg = lane >> 4;

    #pragma unroll 1
    for (int it = 0; it < G1_ITERS; it++) {
        CP_ASYNC_WAIT(2);
        __syncthreads();
        const int buf = it & 3;
        const uint32_t sa = sb + buf * STAGE_B;
        const uint32_t sB = sa + TILE_HALF * 2;

        // issue next stage loads early (overwrites stage (it-1)&3, already consumed)
        if (it + 3 < G1_ITERS) load_stage((it + 3) & 3, (it + 3) * 32);
        CP_ASYNC_COMMIT();

        #pragma unroll
        for (int ks = 0; ks < 2; ks++) {
            const uint32_t koff = (ks * 16 + lseg * 8) * 2;
            uint32_t a[4][4];
            #pragma unroll
            for (int mt = 0; mt < 4; mt++) {
                uint32_t ad = sa + (uint32_t)(wm * 64 + mt * 16 + lrow) * ROWB + koff;
                LDSM_X4(a[mt][0], a[mt][1], a[mt][2], a[mt][3], ad);
            }
            uint32_t bfr[2][4];
            #pragma unroll
            for (int nb = 0; nb < 2; nb++) {
                uint32_t bd = sB + (uint32_t)(wn * 32 + nb * 16 + lrow) * ROWB + koff;
                LDSM_X4(bfr[nb][0], bfr[nb][1], bfr[nb][2], bfr[nb][3], bd);
            }
            // fragment regs: [0]=(n0-7,k0-7) [1]=(n8-15,k0-7) [2]=(n0-7,k8-15) [3]=(n8-15,k8-15)
            #pragma unroll
            for (int mt = 0; mt < 4; mt++)
                #pragma unroll
                for (int nt = 0; nt < 4; nt++) {
                    const int nb = nt >> 1, rs = nt & 1;
                    MMA_BF16(acc[mt][nt][0], acc[mt][nt][1], acc[mt][nt][2], acc[mt][nt][3],
                             a[mt][0], a[mt][1], a[mt][2], a[mt][3],
                             bfr[nb][rs], bfr[nb][rs + 2]);
                }
        }
        __syncthreads();
    }

    // Epilogue: bias + relu, column sums over the CTA's 128 rows.
    // acc regs: [0]=(r,c) [1]=(r,c+1) [2]=(r+8,c) [3]=(r+8,c+1); r=lane/4, c=(lane%4)*2.
    float* sred = (float*)(smem + SRED_OFF);    // [8 warps][32 cols]
    #pragma unroll
    for (int nt = 0; nt < 4; nt++) {
        #pragma unroll
        for (int j = 0; j < 2; j++) {
            const int colL = nt * 8 + (lane & 3) * 2 + j;
            const float bb = bias[col0 + wn * 32 + colL];
            float s = 0.f;
            #pragma unroll
            for (int mt = 0; mt < 4; mt++)
                s += fmaxf(acc[mt][nt][j] + bb, 0.f) + fmaxf(acc[mt][nt][j + 2] + bb, 0.f);
            s += __shfl_down_sync(0xffffffffu, s, 16);
            s += __shfl_down_sync(0xffffffffu, s, 8);
            s += __shfl_down_sync(0xffffffffu, s, 4);
            if ((lane >> 2) == 0) sred[warp * 32 + colL] = s;
        }
    }
    __syncthreads();
    if (tid < 128) {
        const int w = tid >> 5, cl = tid & 31;
        g_partial[mtile * N1 + col0 + tid] = sred[w * 32 + cl] + sred[(w + 4) * 32 + cl];
    }
}

// u[j] = sum over 16 M-blocks
__global__ void reduce_u_kernel()
{
    int j = blockIdx.x * 256 + threadIdx.x;
    if (j < N1) {
        float s = 0.f;
        #pragma unroll
        for (int m = 0; m < 16; m++) s += g_partial[m * N1 + j];
        g_u[j] = s;
    }
}

// g_T[c] = u . W_fc[c, HD:] + 2048*b_fc[c]
__global__ void s2_kernel(const float* __restrict__ Wfc, const float* __restrict__ bfc)
{
    __shared__ float red[128];
    const int c = blockIdx.x, tid = threadIdx.x;
    const float* w = Wfc + (size_t)c * WLD + HD;
    float p = 0.f;
    for (int k = tid; k < N1; k += 128) p += g_u[k] * w[k];
    red[tid] = p;
    __syncthreads();
    for (int s = 64; s > 0; s >>= 1) {
        if (tid < s) red[tid] += red[tid + s];
        __syncthreads();
    }
    if (tid == 0) g_T[c] = red[0] + 2048.f * bfc[c];
}

// ---------------------------------------------------------------------------
// s1 = z1 @ W_fc[:, :HD]^T, split-K 16 slices of 128.
// ---------------------------------------------------------------------------
__global__ __launch_bounds__(256, 2) void s1_kernel(
    const float* __restrict__ A, const float* __restrict__ W)
{
    __shared__ float As[16][132];
    __shared__ float Bs[16][68];

    const int tid   = threadIdx.x;
    const int cg    = tid & 15;
    const int rg    = tid >> 4;
    const int row0  = blockIdx.x * 128;
    const int kbase = blockIdx.y * 128;

    const int lrow = tid >> 2;
    const int lq   = tid & 3;
    const float* Aptr0 = A + (size_t)(row0 + lrow) * HD + kbase + lq * 4;
    const float* Aptr1 = Aptr0 + (size_t)64 * HD;

    float acc[8][5];
    #pragma unroll
    for (int r = 0; r < 8; r++)
        #pragma unroll
        for (int j = 0; j < 5; j++) acc[r][j] = 0.f;

    for (int kk = 0; kk < 128; kk += 16) {
        __syncthreads();
        {
            float4 a0 = *(const float4*)(Aptr0 + kk);
            float4 a1 = *(const float4*)(Aptr1 + kk);
            As[lq*4+0][lrow]    = a0.x; As[lq*4+1][lrow]    = a0.y;
            As[lq*4+2][lrow]    = a0.z; As[lq*4+3][lrow]    = a0.w;
            As[lq*4+0][lrow+64] = a1.x; As[lq*4+1][lrow+64] = a1.y;
            As[lq*4+2][lrow+64] = a1.z; As[lq*4+3][lrow+64] = a1.w;
        }
        for (int f = tid; f < NC * 4; f += 256) {
            int n = f >> 2, q = f & 3;
            float4 w = *(const float4*)(W + (size_t)n * WLD + kbase + kk + q * 4);
            Bs[q*4+0][n] = w.x; Bs[q*4+1][n] = w.y;
            Bs[q*4+2][n] = w.z; Bs[q*4+3][n] = w.w;
        }
        __syncthreads();

        if (cg < 13) {
            #pragma unroll
            for (int k = 0; k < 16; k++) {
                float4 av0 = *(const float4*)(&As[k][rg*8]);
                float4 av1 = *(const float4*)(&As[k][rg*8+4]);
                float a[8] = {av0.x,av0.y,av0.z,av0.w,av1.x,av1.y,av1.z,av1.w};
                #pragma unroll
                for (int j = 0; j < 5; j++) {
                    float b = Bs[k][cg*5 + j];
                    #pragma unroll
                    for (int r = 0; r < 8; r++)
                        acc[r][j] += a[r] * b;
                }
            }
        }
    }

    if (cg < 13) {
        #pragma unroll
        for (int r = 0; r < 8; r++)
            #pragma unroll
            for (int j = 0; j < 5; j++)
                g_s1part[(size_t)blockIdx.y * (BSZ * NC)
                         + (size_t)(row0 + rg*8 + r) * NC + cg*5 + j] = acc[r][j];
    }
}

// out[i,c] = 2048 * s1[i,c] + g_T[c]
__global__ void out_kernel(float* __restrict__ out)
{
    int idx = blockIdx.x * 256 + threadIdx.x;
    if (idx < BSZ * NC) {
        int c = idx % NC;
        float s = 0.f;
        #pragma unroll
        for (int sl = 0; sl < KSPLIT; sl++) s += g_s1part[sl * (BSZ * NC) + idx];
        out[idx] = 2048.f * s + g_T[c];
    }
}

extern "C" void kernel_launch(void* const* d_in, const int* in_sizes, int n_in,
                              void* d_out, int out_size)
{
    const float* z1  = (const float*)d_in[0];
    const float* z2  = (const float*)d_in[1];
    const float* Wp  = (const float*)d_in[2];
    const float* bp  = (const float*)d_in[3];
    const float* Wfc = (const float*)d_in[4];
    const float* bfc = (const float*)d_in[5];
    float* out = (float*)d_out;

    cudaFuncSetAttribute(gemm1_tc, cudaFuncAttributeMaxDynamicSharedMemorySize, G1_SMEM);

    __nv_bfloat16* Abf = nullptr;
    __nv_bfloat16* Bbf = nullptr;
    cudaGetSymbolAddress((void**)&Abf, g_Abf);
    cudaGetSymbolAddress((void**)&Bbf, g_Bbf);

    convert_kernel<<<1184, 256>>>(z2, Abf, (BSZ * K1) / 4);
    convert_kernel<<<592,  256>>>(Wp, Bbf, (N1 * K1) / 4);
    gemm1_tc<<<128, 256, G1_SMEM>>>(Abf, Bbf, bp);
    reduce_u_kernel<<<4, 256>>>();
    s2_kernel<<<NC, 128>>>(Wfc, bfc);
    s1_kernel<<<dim3(16, KSPLIT), 256>>>(z1, Wfc);
    out_kernel<<<(BSZ * NC + 255) / 256, 256>>>(out);
}

// round 6
// speedup vs baseline: 4.4714x; 1.1169x over previous
#include <cuda_runtime.h>
#include <cuda_bf16.h>
#include <cstdint>

// Problem constants
#define BSZ   2048
#define K1    9408     // 3*56*56
#define N1    1024     // PROJ_OUT
#define HD    2048     // HIDDEN_DIM
#define NC    65       // N_CLASSES
#define WLD   3072     // W_fc leading dim
#define KSPLIT 16      // s1 split-K slices

// ---------------------------------------------------------------------------
// PTX helpers (baseline ISA only)
// ---------------------------------------------------------------------------
__device__ __forceinline__ uint32_t smem_to_u32(const void* p) {
    uint32_t a;
    asm("{ .reg .u64 t; cvta.to.shared.u64 t, %1; cvt.u32.u64 %0, t; }" : "=r"(a) : "l"(p));
    return a;
}
#define CP_ASYNC_16(dst, src) \
    asm volatile("cp.async.cg.shared.global [%0], [%1], 16;" :: "r"(dst), "l"(src))
#define CP_ASYNC_COMMIT() asm volatile("cp.async.commit_group;" ::: "memory")
#define CP_ASYNC_WAIT(n)  asm volatile("cp.async.wait_group %0;" :: "n"(n) : "memory")

#define LDSM_X4(r0,r1,r2,r3,addr) \
    asm volatile("ldmatrix.sync.aligned.m8n8.x4.shared.b16 {%0,%1,%2,%3}, [%4];" \
        : "=r"(r0),"=r"(r1),"=r"(r2),"=r"(r3) : "r"(addr))

#define MMA_BF16(c0,c1,c2,c3,a0,a1,a2,a3,b0,b1) \
    asm volatile("mma.sync.aligned.m16n8k16.row.col.f32.bf16.bf16.f32 " \
        "{%0,%1,%2,%3}, {%4,%5,%6,%7}, {%8,%9}, {%0,%1,%2,%3};" \
        : "+f"(c0),"+f"(c1),"+f"(c2),"+f"(c3) \
        : "r"(a0),"r"(a1),"r"(a2),"r"(a3), "r"(b0),"r"(b1))

// ---------------------------------------------------------------------------
// Scratch
// ---------------------------------------------------------------------------
__device__ __nv_bfloat16 g_Abf[(size_t)BSZ * K1];   // z2f bf16 (38.5 MB)
__device__ __nv_bfloat16 g_Bbf[(size_t)N1 * K1];    // W_proj bf16 (19.3 MB)
__device__ float g_partial[16 * N1];                // per-M-block column sums
__device__ float g_T[NC];
__device__ float g_s1part[KSPLIT * BSZ * NC];

// ---------------------------------------------------------------------------
// fp32 -> bf16 conversion: both tensors in one launch (device globals as dst).
// ---------------------------------------------------------------------------
#define NA4 ((BSZ * K1) / 4)
#define NB4 ((N1 * K1) / 4)
__global__ void convert_kernel(const float* __restrict__ srcA, const float* __restrict__ srcB)
{
    int i = blockIdx.x * blockDim.x + threadIdx.x;
    const int stride = gridDim.x * blockDim.x;
    for (; i < NA4 + NB4; i += stride) {
        const float4* sp;
        uint2* dp;
        if (i < NA4) { sp = (const float4*)srcA + i; dp = (uint2*)g_Abf + i; }
        else         { sp = (const float4*)srcB + (i - NA4); dp = (uint2*)g_Bbf + (i - NA4); }
        float4 f = *sp;
        __nv_bfloat162 lo = __floats2bfloat162_rn(f.x, f.y);
        __nv_bfloat162 hi = __floats2bfloat162_rn(f.z, f.w);
        uint2 v;
        v.x = *(uint32_t*)&lo;
        v.y = *(uint32_t*)&hi;
        *dp = v;
    }
}

// ---------------------------------------------------------------------------
// GEMM1 via mma.sync bf16: relu(A@B^T + bias) reduced to column sums.
// CTA tile 128x128, BK=64, 8 warps (2x4), 3-stage cp.async, one barrier/iter.
// ---------------------------------------------------------------------------
#define G1_ITERS   147                 // 9408 / 64
#define ROWB       144                 // 64 bf16 (128B) + 16B pad
#define TILE_B     (128 * ROWB)        // 18432 bytes per operand tile
#define STAGE_B    (2 * TILE_B)        // 36864 bytes per stage
#define NSTAGE     3
#define SRED_OFF   (NSTAGE * STAGE_B)  // 110592
#define G1_SMEM    (SRED_OFF + 8 * 32 * 4)

__global__ __launch_bounds__(256, 1) void gemm1_tc(
    const __nv_bfloat16* __restrict__ Ag, const __nv_bfloat16* __restrict__ Bg,
    const float* __restrict__ bias)
{
    extern __shared__ char smem[];
    const uint32_t sb = smem_to_u32(smem);
    const int tid  = threadIdx.x;
    const int lane = tid & 31;
    const int warp = tid >> 5;
    const int wm   = warp >> 2;        // 0..1  (M 64-half)
    const int wn   = warp & 3;         // 0..3  (N 32-quarter)
    const int mtile = blockIdx.x & 15;
    const int ntile = blockIdx.x >> 4;
    const int row0 = mtile * 128;
    const int col0 = ntile * 128;

    // stage loader: 1024 A + 1024 B chunks of 16B -> 4 A + 4 B per thread
    auto load_stage = [&](int buf, int k0) {
        const uint32_t sa = sb + buf * STAGE_B;
        const uint32_t sB = sa + TILE_B;
        #pragma unroll
        for (int i = 0; i < 4; i++) {
            const int v = tid + i * 256;     // 0..1023
            const int r = v >> 3, c = v & 7;
            CP_ASYNC_16(sa + r * ROWB + c * 16,
                        Ag + (size_t)(row0 + r) * K1 + k0 + c * 8);
            CP_ASYNC_16(sB + r * ROWB + c * 16,
                        Bg + (size_t)(col0 + r) * K1 + k0 + c * 8);
        }
    };

    float acc[4][4][4];
    #pragma unroll
    for (int mt = 0; mt < 4; mt++)
        #pragma unroll
        for (int nt = 0; nt < 4; nt++)
            #pragma unroll
            for (int q = 0; q < 4; q++) acc[mt][nt][q] = 0.f;

    // prefetch 2 stages
    load_stage(0, 0);  CP_ASYNC_COMMIT();
    load_stage(1, 64); CP_ASYNC_COMMIT();

    const int lrow = lane & 15;
    const int lseg = lane >> 4;

    int buf = 0;
    #pragma unroll 1
    for (int it = 0; it < G1_ITERS; it++) {
        CP_ASYNC_WAIT(1);
        __syncthreads();               // single barrier per iteration
        const uint32_t sa = sb + buf * STAGE_B;
        const uint32_t sB = sa + TILE_B;

        if (it + 2 < G1_ITERS) {
            int nb = buf + 2; if (nb >= 3) nb -= 3;
            load_stage(nb, (it + 2) * 64);
        }
        CP_ASYNC_COMMIT();

        #pragma unroll
        for (int ks = 0; ks < 4; ks++) {
            const uint32_t koff = ks * 32 + lseg * 16;
            uint32_t a[4][4];
            #pragma unroll
            for (int mt = 0; mt < 4; mt++) {
                uint32_t ad = sa + (uint32_t)(wm * 64 + mt * 16 + lrow) * ROWB + koff;
                LDSM_X4(a[mt][0], a[mt][1], a[mt][2], a[mt][3], ad);
            }
            uint32_t bfr[2][4];
            #pragma unroll
            for (int nb2 = 0; nb2 < 2; nb2++) {
                uint32_t bd = sB + (uint32_t)(wn * 32 + nb2 * 16 + lrow) * ROWB + koff;
                LDSM_X4(bfr[nb2][0], bfr[nb2][1], bfr[nb2][2], bfr[nb2][3], bd);
            }
            #pragma unroll
            for (int mt = 0; mt < 4; mt++)
                #pragma unroll
                for (int nt = 0; nt < 4; nt++) {
                    const int nb2 = nt >> 1, rs = nt & 1;
                    MMA_BF16(acc[mt][nt][0], acc[mt][nt][1], acc[mt][nt][2], acc[mt][nt][3],
                             a[mt][0], a[mt][1], a[mt][2], a[mt][3],
                             bfr[nb2][rs], bfr[nb2][rs + 2]);
                }
        }
        buf++; if (buf >= 3) buf = 0;
    }

    // Epilogue: bias + relu, column sums over the CTA's 128 rows.
    float* sred = (float*)(smem + SRED_OFF);    // [8 warps][32 cols]
    #pragma unroll
    for (int nt = 0; nt < 4; nt++) {
        #pragma unroll
        for (int j = 0; j < 2; j++) {
            const int colL = nt * 8 + (lane & 3) * 2 + j;
            const float bb = bias[col0 + wn * 32 + colL];
            float s = 0.f;
            #pragma unroll
            for (int mt = 0; mt < 4; mt++)
                s += fmaxf(acc[mt][nt][j] + bb, 0.f) + fmaxf(acc[mt][nt][j + 2] + bb, 0.f);
            s += __shfl_down_sync(0xffffffffu, s, 16);
            s += __shfl_down_sync(0xffffffffu, s, 8);
            s += __shfl_down_sync(0xffffffffu, s, 4);
            if ((lane >> 2) == 0) sred[warp * 32 + colL] = s;
        }
    }
    __syncthreads();
    if (tid < 128) {
        const int w = tid >> 5, cl = tid & 31;
        g_partial[mtile * N1 + col0 + tid] = sred[w * 32 + cl] + sred[(w + 4) * 32 + cl];
    }
}

// g_T[c] = (Σ_m g_partial[m]) . W_fc[c, HD:] + 2048*b_fc[c]   (u on the fly)
__global__ void s2_kernel(const float* __restrict__ Wfc, const float* __restrict__ bfc)
{
    __shared__ float red[128];
    const int c = blockIdx.x, tid = threadIdx.x;
    const float* w = Wfc + (size_t)c * WLD + HD;
    float p = 0.f;
    for (int k = tid; k < N1; k += 128) {
        float u = 0.f;
        #pragma unroll
        for (int m = 0; m < 16; m++) u += g_partial[m * N1 + k];
        p += u * w[k];
    }
    red[tid] = p;
    __syncthreads();
    for (int s = 64; s > 0; s >>= 1) {
        if (tid < s) red[tid] += red[tid + s];
        __syncthreads();
    }
    if (tid == 0) g_T[c] = red[0] + 2048.f * bfc[c];
}

// ---------------------------------------------------------------------------
// s1 = z1 @ W_fc[:, :HD]^T, split-K 16 slices of 128.
// ---------------------------------------------------------------------------
__global__ __launch_bounds__(256, 2) void s1_kernel(
    const float* __restrict__ A, const float* __restrict__ W)
{
    __shared__ float As[16][132];
    __shared__ float Bs[16][68];

    const int tid   = threadIdx.x;
    const int cg    = tid & 15;
    const int rg    = tid >> 4;
    const int row0  = blockIdx.x * 128;
    const int kbase = blockIdx.y * 128;

    const int lrow = tid >> 2;
    const int lq   = tid & 3;
    const float* Aptr0 = A + (size_t)(row0 + lrow) * HD + kbase + lq * 4;
    const float* Aptr1 = Aptr0 + (size_t)64 * HD;

    float acc[8][5];
    #pragma unroll
    for (int r = 0; r < 8; r++)
        #pragma unroll
        for (int j = 0; j < 5; j++) acc[r][j] = 0.f;

    for (int kk = 0; kk < 128; kk += 16) {
        __syncthreads();
        {
            float4 a0 = *(const float4*)(Aptr0 + kk);
            float4 a1 = *(const float4*)(Aptr1 + kk);
            As[lq*4+0][lrow]    = a0.x; As[lq*4+1][lrow]    = a0.y;
            As[lq*4+2][lrow]    = a0.z; As[lq*4+3][lrow]    = a0.w;
            As[lq*4+0][lrow+64] = a1.x; As[lq*4+1][lrow+64] = a1.y;
            As[lq*4+2][lrow+64] = a1.z; As[lq*4+3][lrow+64] = a1.w;
        }
        for (int f = tid; f < NC * 4; f += 256) {
            int n = f >> 2, q = f & 3;
            float4 w = *(const float4*)(W + (size_t)n * WLD + kbase + kk + q * 4);
            Bs[q*4+0][n] = w.x; Bs[q*4+1][n] = w.y;
            Bs[q*4+2][n] = w.z; Bs[q*4+3][n] = w.w;
        }
        __syncthreads();

        if (cg < 13) {
            #pragma unroll
            for (int k = 0; k < 16; k++) {
                float4 av0 = *(const float4*)(&As[k][rg*8]);
                float4 av1 = *(const float4*)(&As[k][rg*8+4]);
                float a[8] = {av0.x,av0.y,av0.z,av0.w,av1.x,av1.y,av1.z,av1.w};
                #pragma unroll
                for (int j = 0; j < 5; j++) {
                    float b = Bs[k][cg*5 + j];
                    #pragma unroll
                    for (int r = 0; r < 8; r++)
                        acc[r][j] += a[r] * b;
                }
            }
        }
    }

    if (cg < 13) {
        #pragma unroll
        for (int r = 0; r < 8; r++)
            #pragma unroll
            for (int j = 0; j < 5; j++)
                g_s1part[(size_t)blockIdx.y * (BSZ * NC)
                         + (size_t)(row0 + rg*8 + r) * NC + cg*5 + j] = acc[r][j];
    }
}

// out[i,c] = 2048 * s1[i,c] + g_T[c]
__global__ void out_kernel(float* __restrict__ out)
{
    int idx = blockIdx.x * 256 + threadIdx.x;
    if (idx < BSZ * NC) {
        int c = idx % NC;
        float s = 0.f;
        #pragma unroll
        for (int sl = 0; sl < KSPLIT; sl++) s += g_s1part[sl * (BSZ * NC) + idx];
        out[idx] = 2048.f * s + g_T[c];
    }
}

extern "C" void kernel_launch(void* const* d_in, const int* in_sizes, int n_in,
                              void* d_out, int out_size)
{
    const float* z1  = (const float*)d_in[0];
    const float* z2  = (const float*)d_in[1];
    const float* Wp  = (const float*)d_in[2];
    const float* bp  = (const float*)d_in[3];
    const float* Wfc = (const float*)d_in[4];
    const float* bfc = (const float*)d_in[5];
    float* out = (float*)d_out;

    cudaFuncSetAttribute(gemm1_tc, cudaFuncAttributeMaxDynamicSharedMemorySize, G1_SMEM);

    // Device addresses of __device__ globals (host-side symbol use is invalid!)
    __nv_bfloat16* Abf = nullptr;
    __nv_bfloat16* Bbf = nullptr;
    cudaGetSymbolAddress((void**)&Abf, g_Abf);
    cudaGetSymbolAddress((void**)&Bbf, g_Bbf);

    convert_kernel<<<1184, 512>>>(z2, Wp);
    gemm1_tc<<<128, 256, G1_SMEM>>>(Abf, Bbf, bp);
    s2_kernel<<<NC, 128>>>(Wfc, bfc);
    s1_kernel<<<dim3(16, KSPLIT), 256>>>(z1, Wfc);
    out_kernel<<<(BSZ * NC + 255) / 256, 256>>>(out);
}

// round 7
// speedup vs baseline: 4.5422x; 1.0158x over previous
#include <cuda_runtime.h>
#include <cuda_bf16.h>
#include <cstdint>

// Problem constants
#define BSZ   2048
#define K1    9408     // 3*56*56
#define N1    1024     // PROJ_OUT
#define HD    2048     // HIDDEN_DIM
#define NC    65       // N_CLASSES
#define WLD   3072     // W_fc leading dim
#define KSPLIT 16      // s1 split-K slices

// ---------------------------------------------------------------------------
// PTX helpers (baseline ISA only)
// ---------------------------------------------------------------------------
__device__ __forceinline__ uint32_t smem_to_u32(const void* p) {
    uint32_t a;
    asm("{ .reg .u64 t; cvta.to.shared.u64 t, %1; cvt.u32.u64 %0, t; }" : "=r"(a) : "l"(p));
    return a;
}
#define CP_ASYNC_16(dst, src) \
    asm volatile("cp.async.cg.shared.global [%0], [%1], 16;" :: "r"(dst), "l"(src))
#define CP_ASYNC_COMMIT() asm volatile("cp.async.commit_group;" ::: "memory")
#define CP_ASYNC_WAIT(n)  asm volatile("cp.async.wait_group %0;" :: "n"(n) : "memory")

#define LDSM_X4(r0,r1,r2,r3,addr) \
    asm volatile("ldmatrix.sync.aligned.m8n8.x4.shared.b16 {%0,%1,%2,%3}, [%4];" \
        : "=r"(r0),"=r"(r1),"=r"(r2),"=r"(r3) : "r"(addr))

#define MMA_BF16(c0,c1,c2,c3,a0,a1,a2,a3,b0,b1) \
    asm volatile("mma.sync.aligned.m16n8k16.row.col.f32.bf16.bf16.f32 " \
        "{%0,%1,%2,%3}, {%4,%5,%6,%7}, {%8,%9}, {%0,%1,%2,%3};" \
        : "+f"(c0),"+f"(c1),"+f"(c2),"+f"(c3) \
        : "r"(a0),"r"(a1),"r"(a2),"r"(a3), "r"(b0),"r"(b1))

// ---------------------------------------------------------------------------
// Scratch
// ---------------------------------------------------------------------------
__device__ __nv_bfloat16 g_Abf[(size_t)BSZ * K1];   // z2f bf16 (38.5 MB)
__device__ __nv_bfloat16 g_Bbf[(size_t)N1 * K1];    // W_proj bf16 (19.3 MB)
__device__ float g_partial[16 * N1];                // per-M-block column sums
__device__ float g_T[NC];
__device__ float g_s1part[KSPLIT * BSZ * NC];

// ---------------------------------------------------------------------------
// fp32 -> bf16 conversion: both tensors in one launch (device globals as dst).
// ---------------------------------------------------------------------------
#define NA4 ((BSZ * K1) / 4)
#define NB4 ((N1 * K1) / 4)
__global__ void convert_kernel(const float* __restrict__ srcA, const float* __restrict__ srcB)
{
    int i = blockIdx.x * blockDim.x + threadIdx.x;
    const int stride = gridDim.x * blockDim.x;
    for (; i < NA4 + NB4; i += stride) {
        const float4* sp;
        uint2* dp;
        if (i < NA4) { sp = (const float4*)srcA + i; dp = (uint2*)g_Abf + i; }
        else         { sp = (const float4*)srcB + (i - NA4); dp = (uint2*)g_Bbf + (i - NA4); }
        float4 f = *sp;
        __nv_bfloat162 lo = __floats2bfloat162_rn(f.x, f.y);
        __nv_bfloat162 hi = __floats2bfloat162_rn(f.z, f.w);
        uint2 v;
        v.x = *(uint32_t*)&lo;
        v.y = *(uint32_t*)&hi;
        *dp = v;
    }
}

// ---------------------------------------------------------------------------
// GEMM1 via mma.sync bf16: relu(A@B^T + bias) reduced to column sums.
// CTA tile 128x128, BK=64, 8 warps (2x4), 3-stage cp.async, one barrier/iter.
// ---------------------------------------------------------------------------
#define G1_ITERS   147                 // 9408 / 64
#define ROWB       144                 // 64 bf16 (128B) + 16B pad
#define TILE_B     (128 * ROWB)        // 18432 bytes per operand tile
#define STAGE_B    (2 * TILE_B)        // 36864 bytes per stage
#define NSTAGE     3
#define SRED_OFF   (NSTAGE * STAGE_B)  // 110592
#define G1_SMEM    (SRED_OFF + 8 * 32 * 4)

__global__ __launch_bounds__(256, 1) void gemm1_tc(
    const __nv_bfloat16* __restrict__ Ag, const __nv_bfloat16* __restrict__ Bg,
    const float* __restrict__ bias)
{
    extern __shared__ char smem[];
    const uint32_t sb = smem_to_u32(smem);
    const int tid  = threadIdx.x;
    const int lane = tid & 31;
    const int warp = tid >> 5;
    const int wm   = warp >> 2;        // 0..1  (M 64-half)
    const int wn   = warp & 3;         // 0..3  (N 32-quarter)
    const int mtile = blockIdx.x & 15;
    const int ntile = blockIdx.x >> 4;
    const int row0 = mtile * 128;
    const int col0 = ntile * 128;

    // stage loader: 1024 A + 1024 B chunks of 16B -> 4 A + 4 B per thread
    auto load_stage = [&](int buf, int k0) {
        const uint32_t sa = sb + buf * STAGE_B;
        const uint32_t sB = sa + TILE_B;
        #pragma unroll
        for (int i = 0; i < 4; i++) {
            const int v = tid + i * 256;     // 0..1023
            const int r = v >> 3, c = v & 7;
            CP_ASYNC_16(sa + r * ROWB + c * 16,
                        Ag + (size_t)(row0 + r) * K1 + k0 + c * 8);
            CP_ASYNC_16(sB + r * ROWB + c * 16,
                        Bg + (size_t)(col0 + r) * K1 + k0 + c * 8);
        }
    };

    float acc[4][4][4];
    #pragma unroll
    for (int mt = 0; mt < 4; mt++)
        #pragma unroll
        for (int nt = 0; nt < 4; nt++)
            #pragma unroll
            for (int q = 0; q < 4; q++) acc[mt][nt][q] = 0.f;

    // prefetch 2 stages
    load_stage(0, 0);  CP_ASYNC_COMMIT();
    load_stage(1, 64); CP_ASYNC_COMMIT();

    const int lrow = lane & 15;
    const int lseg = lane >> 4;

    int buf = 0;
    #pragma unroll 1
    for (int it = 0; it < G1_ITERS; it++) {
        CP_ASYNC_WAIT(1);
        __syncthreads();               // single barrier per iteration
        const uint32_t sa = sb + buf * STAGE_B;
        const uint32_t sB = sa + TILE_B;

        if (it + 2 < G1_ITERS) {
            int nb = buf + 2; if (nb >= 3) nb -= 3;
            load_stage(nb, (it + 2) * 64);
        }
        CP_ASYNC_COMMIT();

        #pragma unroll
        for (int ks = 0; ks < 4; ks++) {
            const uint32_t koff = ks * 32 + lseg * 16;
            uint32_t a[4][4];
            #pragma unroll
            for (int mt = 0; mt < 4; mt++) {
                uint32_t ad = sa + (uint32_t)(wm * 64 + mt * 16 + lrow) * ROWB + koff;
                LDSM_X4(a[mt][0], a[mt][1], a[mt][2], a[mt][3], ad);
            }
            uint32_t bfr[2][4];
            #pragma unroll
            for (int nb2 = 0; nb2 < 2; nb2++) {
                uint32_t bd = sB + (uint32_t)(wn * 32 + nb2 * 16 + lrow) * ROWB + koff;
                LDSM_X4(bfr[nb2][0], bfr[nb2][1], bfr[nb2][2], bfr[nb2][3], bd);
            }
            #pragma unroll
            for (int mt = 0; mt < 4; mt++)
                #pragma unroll
                for (int nt = 0; nt < 4; nt++) {
                    const int nb2 = nt >> 1, rs = nt & 1;
                    MMA_BF16(acc[mt][nt][0], acc[mt][nt][1], acc[mt][nt][2], acc[mt][nt][3],
                             a[mt][0], a[mt][1], a[mt][2], a[mt][3],
                             bfr[nb2][rs], bfr[nb2][rs + 2]);
                }
        }
        buf++; if (buf >= 3) buf = 0;
    }

    // Epilogue: bias + relu, column sums over the CTA's 128 rows.
    float* sred = (float*)(smem + SRED_OFF);    // [8 warps][32 cols]
    #pragma unroll
    for (int nt = 0; nt < 4; nt++) {
        #pragma unroll
        for (int j = 0; j < 2; j++) {
            const int colL = nt * 8 + (lane & 3) * 2 + j;
            const float bb = bias[col0 + wn * 32 + colL];
            float s = 0.f;
            #pragma unroll
            for (int mt = 0; mt < 4; mt++)
                s += fmaxf(acc[mt][nt][j] + bb, 0.f) + fmaxf(acc[mt][nt][j + 2] + bb, 0.f);
            s += __shfl_down_sync(0xffffffffu, s, 16);
            s += __shfl_down_sync(0xffffffffu, s, 8);
            s += __shfl_down_sync(0xffffffffu, s, 4);
            if ((lane >> 2) == 0) sred[warp * 32 + colL] = s;
        }
    }
    __syncthreads();
    if (tid < 128) {
        const int w = tid >> 5, cl = tid & 31;
        g_partial[mtile * N1 + col0 + tid] = sred[w * 32 + cl] + sred[(w + 4) * 32 + cl];
    }
}

// g_T[c] = (Σ_m g_partial[m]) . W_fc[c, HD:] + 2048*b_fc[c]   (u on the fly)
__global__ void s2_kernel(const float* __restrict__ Wfc, const float* __restrict__ bfc)
{
    __shared__ float red[128];
    const int c = blockIdx.x, tid = threadIdx.x;
    const float* w = Wfc + (size_t)c * WLD + HD;
    float p = 0.f;
    for (int k = tid; k < N1; k += 128) {
        float u = 0.f;
        #pragma unroll
        for (int m = 0; m < 16; m++) u += g_partial[m * N1 + k];
        p += u * w[k];
    }
    red[tid] = p;
    __syncthreads();
    for (int s = 64; s > 0; s >>= 1) {
        if (tid < s) red[tid] += red[tid + s];
        __syncthreads();
    }
    if (tid == 0) g_T[c] = red[0] + 2048.f * bfc[c];
}

// ---------------------------------------------------------------------------
// s1 = z1 @ W_fc[:, :HD]^T, split-K 16 slices of 128.
// ---------------------------------------------------------------------------
__global__ __launch_bounds__(256, 2) void s1_kernel(
    const float* __restrict__ A, const float* __restrict__ W)
{
    __shared__ float As[16][132];
    __shared__ float Bs[16][68];

    const int tid   = threadIdx.x;
    const int cg    = tid & 15;
    const int rg    = tid >> 4;
    const int row0  = blockIdx.x * 128;
    const int kbase = blockIdx.y * 128;

    const int lrow = tid >> 2;
    const int lq   = tid & 3;
    const float* Aptr0 = A + (size_t)(row0 + lrow) * HD + kbase + lq * 4;
    const float* Aptr1 = Aptr0 + (size_t)64 * HD;

    float acc[8][5];
    #pragma unroll
    for (int r = 0; r < 8; r++)
        #pragma unroll
        for (int j = 0; j < 5; j++) acc[r][j] = 0.f;

    for (int kk = 0; kk < 128; kk += 16) {
        __syncthreads();
        {
            float4 a0 = *(const float4*)(Aptr0 + kk);
            float4 a1 = *(const float4*)(Aptr1 + kk);
            As[lq*4+0][lrow]    = a0.x; As[lq*4+1][lrow]    = a0.y;
            As[lq*4+2][lrow]    = a0.z; As[lq*4+3][lrow]    = a0.w;
            As[lq*4+0][lrow+64] = a1.x; As[lq*4+1][lrow+64] = a1.y;
            As[lq*4+2][lrow+64] = a1.z; As[lq*4+3][lrow+64] = a1.w;
        }
        for (int f = tid; f < NC * 4; f += 256) {
            int n = f >> 2, q = f & 3;
            float4 w = *(const float4*)(W + (size_t)n * WLD + kbase + kk + q * 4);
            Bs[q*4+0][n] = w.x; Bs[q*4+1][n] = w.y;
            Bs[q*4+2][n] = w.z; Bs[q*4+3][n] = w.w;
        }
        __syncthreads();

        if (cg < 13) {
            #pragma unroll
            for (int k = 0; k < 16; k++) {
                float4 av0 = *(const float4*)(&As[k][rg*8]);
                float4 av1 = *(const float4*)(&As[k][rg*8+4]);
                float a[8] = {av0.x,av0.y,av0.z,av0.w,av1.x,av1.y,av1.z,av1.w};
                #pragma unroll
                for (int j = 0; j < 5; j++) {
                    float b = Bs[k][cg*5 + j];
                    #pragma unroll
                    for (int r = 0; r < 8; r++)
                        acc[r][j] += a[r] * b;
                }
            }
        }
    }

    if (cg < 13) {
        #pragma unroll
        for (int r = 0; r < 8; r++)
            #pragma unroll
            for (int j = 0; j < 5; j++)
                g_s1part[(size_t)blockIdx.y * (BSZ * NC)
                         + (size_t)(row0 + rg*8 + r) * NC + cg*5 + j] = acc[r][j];
    }
}

// out[i,c] = 2048 * s1[i,c] + g_T[c]
__global__ void out_kernel(float* __restrict__ out)
{
    int idx = blockIdx.x * 256 + threadIdx.x;
    if (idx < BSZ * NC) {
        int c = idx % NC;
        float s = 0.f;
        #pragma unroll
        for (int sl = 0; sl < KSPLIT; sl++) s += g_s1part[sl * (BSZ * NC) + idx];
        out[idx] = 2048.f * s + g_T[c];
    }
}

extern "C" void kernel_launch(void* const* d_in, const int* in_sizes, int n_in,
                              void* d_out, int out_size)
{
    const float* z1  = (const float*)d_in[0];
    const float* z2  = (const float*)d_in[1];
    const float* Wp  = (const float*)d_in[2];
    const float* bp  = (const float*)d_in[3];
    const float* Wfc = (const float*)d_in[4];
    const float* bfc = (const float*)d_in[5];
    float* out = (float*)d_out;

    cudaFuncSetAttribute(gemm1_tc, cudaFuncAttributeMaxDynamicSharedMemorySize, G1_SMEM);

    // Device addresses of __device__ globals
    __nv_bfloat16* Abf = nullptr;
    __nv_bfloat16* Bbf = nullptr;
    cudaGetSymbolAddress((void**)&Abf, g_Abf);
    cudaGetSymbolAddress((void**)&Bbf, g_Bbf);

    // Side stream + events, created once (no device memory involved).
    // s1 is independent of convert->gemm1->s2; run it concurrently so its
    // ~31us hides under the tensor-core chain (which leaves 20 SMs idle).
    static cudaStream_t s_side = nullptr;
    static cudaEvent_t  ev_fork = nullptr, ev_join = nullptr;
    if (s_side == nullptr) {
        cudaStreamCreateWithFlags(&s_side, cudaStreamNonBlocking);
        cudaEventCreateWithFlags(&ev_fork, cudaEventDisableTiming);
        cudaEventCreateWithFlags(&ev_join, cudaEventDisableTiming);
    }

    // Fork: side stream inherits capture via event wait.
    cudaEventRecord(ev_fork, 0);
    cudaStreamWaitEvent(s_side, ev_fork, 0);

    // Side branch: s1 (fp32, SIMT)
    s1_kernel<<<dim3(16, KSPLIT), 256, 0, s_side>>>(z1, Wfc);
    cudaEventRecord(ev_join, s_side);

    // Main branch: convert -> gemm1 -> s2 (tensor/bandwidth chain)
    convert_kernel<<<1184, 512>>>(z2, Wp);
    gemm1_tc<<<128, 256, G1_SMEM>>>(Abf, Bbf, bp);
    s2_kernel<<<NC, 128>>>(Wfc, bfc);

    // Join, then combine.
    cudaStreamWaitEvent(0, ev_join, 0);
    out_kernel<<<(BSZ * NC + 255) / 256, 256>>>(out);
}

// round 8
// speedup vs baseline: 4.8085x; 1.0586x over previous
#include <cuda_runtime.h>
#include <cuda_bf16.h>
#include <cstdint>

// Problem constants
#define BSZ   2048
#define K1    9408     // 3*56*56
#define N1    1024     // PROJ_OUT
#define HD    2048     // HIDDEN_DIM
#define NC    65       // N_CLASSES
#define WLD   3072     // W_fc leading dim
#define KSPLIT 16      // s1 split-K slices

// ---------------------------------------------------------------------------
// PTX helpers (baseline ISA only)
// ---------------------------------------------------------------------------
__device__ __forceinline__ uint32_t smem_to_u32(const void* p) {
    uint32_t a;
    asm("{ .reg .u64 t; cvta.to.shared.u64 t, %1; cvt.u32.u64 %0, t; }" : "=r"(a) : "l"(p));
    return a;
}
#define CP_ASYNC_16(dst, src) \
    asm volatile("cp.async.cg.shared.global [%0], [%1], 16;" :: "r"(dst), "l"(src))
#define CP_ASYNC_COMMIT() asm volatile("cp.async.commit_group;" ::: "memory")
#define CP_ASYNC_WAIT(n)  asm volatile("cp.async.wait_group %0;" :: "n"(n) : "memory")

#define LDSM_X4(r0,r1,r2,r3,addr) \
    asm volatile("ldmatrix.sync.aligned.m8n8.x4.shared.b16 {%0,%1,%2,%3}, [%4];" \
        : "=r"(r0),"=r"(r1),"=r"(r2),"=r"(r3) : "r"(addr))

#define MMA_BF16(c0,c1,c2,c3,a0,a1,a2,a3,b0,b1) \
    asm volatile("mma.sync.aligned.m16n8k16.row.col.f32.bf16.bf16.f32 " \
        "{%0,%1,%2,%3}, {%4,%5,%6,%7}, {%8,%9}, {%0,%1,%2,%3};" \
        : "+f"(c0),"+f"(c1),"+f"(c2),"+f"(c3) \
        : "r"(a0),"r"(a1),"r"(a2),"r"(a3), "r"(b0),"r"(b1))

// ---------------------------------------------------------------------------
// Scratch
// ---------------------------------------------------------------------------
__device__ __nv_bfloat16 g_Abf[(size_t)BSZ * K1];   // z2f bf16 (38.5 MB)
__device__ __nv_bfloat16 g_Bbf[(size_t)N1 * K1];    // W_proj bf16 (19.3 MB)
__device__ float g_partial[16 * N1];                // per-M-block column sums
__device__ float g_T[NC];
__device__ float g_s1part[KSPLIT * BSZ * NC];

// ---------------------------------------------------------------------------
// fp32 -> bf16 conversion: both tensors in one launch (device globals as dst).
// ---------------------------------------------------------------------------
#define NA4 ((BSZ * K1) / 4)
#define NB4 ((N1 * K1) / 4)
__global__ void convert_kernel(const float* __restrict__ srcA, const float* __restrict__ srcB)
{
    int i = blockIdx.x * blockDim.x + threadIdx.x;
    const int stride = gridDim.x * blockDim.x;
    for (; i < NA4 + NB4; i += stride) {
        const float4* sp;
        uint2* dp;
        if (i < NA4) { sp = (const float4*)srcA + i; dp = (uint2*)g_Abf + i; }
        else         { sp = (const float4*)srcB + (i - NA4); dp = (uint2*)g_Bbf + (i - NA4); }
        float4 f = *sp;
        __nv_bfloat162 lo = __floats2bfloat162_rn(f.x, f.y);
        __nv_bfloat162 hi = __floats2bfloat162_rn(f.z, f.w);
        uint2 v;
        v.x = *(uint32_t*)&lo;
        v.y = *(uint32_t*)&hi;
        *dp = v;
    }
}

// ---------------------------------------------------------------------------
// GEMM1 via mma.sync bf16: relu(A@B^T + bias) reduced to column sums.
// CTA tile 128x128, BK=64, 16 warps (4x4, warp tile 32x32), 3-stage cp.async.
// 4 warps per SMSP for latency hiding; short per-warp dependency chains.
// ---------------------------------------------------------------------------
#define G1_ITERS   147                 // 9408 / 64
#define ROWB       144                 // 64 bf16 (128B) + 16B pad
#define TILE_B     (128 * ROWB)        // 18432 bytes per operand tile
#define STAGE_B    (2 * TILE_B)        // 36864 bytes per stage
#define NSTAGE     3
#define SRED_OFF   (NSTAGE * STAGE_B)  // 110592
#define G1_SMEM    (SRED_OFF + 16 * 32 * 4)

__global__ __launch_bounds__(512, 1) void gemm1_tc(
    const __nv_bfloat16* __restrict__ Ag, const __nv_bfloat16* __restrict__ Bg,
    const float* __restrict__ bias)
{
    extern __shared__ char smem[];
    const uint32_t sb = smem_to_u32(smem);
    const int tid  = threadIdx.x;
    const int lane = tid & 31;
    const int warp = tid >> 5;         // 0..15
    const int wm   = warp >> 2;        // 0..3  (M 32-row strip)
    const int wn   = warp & 3;         // 0..3  (N 32-col strip)
    const int mtile = blockIdx.x & 15;
    const int ntile = blockIdx.x >> 4;
    const int row0 = mtile * 128;
    const int col0 = ntile * 128;

    // stage loader: 1024 A + 1024 B chunks of 16B -> 2 A + 2 B per thread
    auto load_stage = [&](int buf, int k0) {
        const uint32_t sa = sb + buf * STAGE_B;
        const uint32_t sB = sa + TILE_B;
        #pragma unroll
        for (int i = 0; i < 2; i++) {
            const int v = tid + i * 512;     // 0..1023
            const int r = v >> 3, c = v & 7;
            CP_ASYNC_16(sa + r * ROWB + c * 16,
                        Ag + (size_t)(row0 + r) * K1 + k0 + c * 8);
            CP_ASYNC_16(sB + r * ROWB + c * 16,
                        Bg + (size_t)(col0 + r) * K1 + k0 + c * 8);
        }
    };

    float acc[2][4][4];
    #pragma unroll
    for (int mt = 0; mt < 2; mt++)
        #pragma unroll
        for (int nt = 0; nt < 4; nt++)
            #pragma unroll
            for (int q = 0; q < 4; q++) acc[mt][nt][q] = 0.f;

    // prefetch 2 stages
    load_stage(0, 0);  CP_ASYNC_COMMIT();
    load_stage(1, 64); CP_ASYNC_COMMIT();

    const int lrow = lane & 15;
    const int lseg = lane >> 4;

    int buf = 0;
    #pragma unroll 1
    for (int it = 0; it < G1_ITERS; it++) {
        CP_ASYNC_WAIT(1);
        __syncthreads();               // single barrier per iteration
        const uint32_t sa = sb + buf * STAGE_B;
        const uint32_t sB = sa + TILE_B;

        if (it + 2 < G1_ITERS) {
            int nb = buf + 2; if (nb >= 3) nb -= 3;
            load_stage(nb, (it + 2) * 64);
        }
        CP_ASYNC_COMMIT();

        #pragma unroll
        for (int ks = 0; ks < 4; ks++) {
            const uint32_t koff = ks * 32 + lseg * 16;
            uint32_t a[2][4];
            #pragma unroll
            for (int mt = 0; mt < 2; mt++) {
                uint32_t ad = sa + (uint32_t)(wm * 32 + mt * 16 + lrow) * ROWB + koff;
                LDSM_X4(a[mt][0], a[mt][1], a[mt][2], a[mt][3], ad);
            }
            uint32_t bfr[2][4];
            #pragma unroll
            for (int nb2 = 0; nb2 < 2; nb2++) {
                uint32_t bd = sB + (uint32_t)(wn * 32 + nb2 * 16 + lrow) * ROWB + koff;
                LDSM_X4(bfr[nb2][0], bfr[nb2][1], bfr[nb2][2], bfr[nb2][3], bd);
            }
            #pragma unroll
            for (int mt = 0; mt < 2; mt++)
                #pragma unroll
                for (int nt = 0; nt < 4; nt++) {
                    const int nb2 = nt >> 1, rs = nt & 1;
                    MMA_BF16(acc[mt][nt][0], acc[mt][nt][1], acc[mt][nt][2], acc[mt][nt][3],
                             a[mt][0], a[mt][1], a[mt][2], a[mt][3],
                             bfr[nb2][rs], bfr[nb2][rs + 2]);
                }
        }
        buf++; if (buf >= 3) buf = 0;
    }

    // Epilogue: bias + relu, column sums over the CTA's 128 rows.
    // acc regs: [0]=(r,c) [1]=(r,c+1) [2]=(r+8,c) [3]=(r+8,c+1); r=lane/4, c=(lane%4)*2.
    float* sred = (float*)(smem + SRED_OFF);    // [16 warps][32 cols]
    #pragma unroll
    for (int nt = 0; nt < 4; nt++) {
        #pragma unroll
        for (int j = 0; j < 2; j++) {
            const int colL = nt * 8 + (lane & 3) * 2 + j;
            const float bb = bias[col0 + wn * 32 + colL];
            float s = 0.f;
            #pragma unroll
            for (int mt = 0; mt < 2; mt++)
                s += fmaxf(acc[mt][nt][j] + bb, 0.f) + fmaxf(acc[mt][nt][j + 2] + bb, 0.f);
            s += __shfl_down_sync(0xffffffffu, s, 16);
            s += __shfl_down_sync(0xffffffffu, s, 8);
            s += __shfl_down_sync(0xffffffffu, s, 4);
            if ((lane >> 2) == 0) sred[warp * 32 + colL] = s;
        }
    }
    __syncthreads();
    if (tid < 128) {
        // global col within tile = tid; wn = tid>>5, colL = tid&31; sum 4 wm strips
        const int wnq = tid >> 5, cl = tid & 31;
        float s = 0.f;
        #pragma unroll
        for (int wmq = 0; wmq < 4; wmq++)
            s += sred[(wmq * 4 + wnq) * 32 + cl];
        g_partial[mtile * N1 + col0 + tid] = s;
    }
}

// g_T[c] = (Σ_m g_partial[m]) . W_fc[c, HD:] + 2048*b_fc[c]   (u on the fly)
__global__ void s2_kernel(const float* __restrict__ Wfc, const float* __restrict__ bfc)
{
    __shared__ float red[128];
    const int c = blockIdx.x, tid = threadIdx.x;
    const float* w = Wfc + (size_t)c * WLD + HD;
    float p = 0.f;
    for (int k = tid; k < N1; k += 128) {
        float u = 0.f;
        #pragma unroll
        for (int m = 0; m < 16; m++) u += g_partial[m * N1 + k];
        p += u * w[k];
    }
    red[tid] = p;
    __syncthreads();
    for (int s = 64; s > 0; s >>= 1) {
        if (tid < s) red[tid] += red[tid + s];
        __syncthreads();
    }
    if (tid == 0) g_T[c] = red[0] + 2048.f * bfc[c];
}

// ---------------------------------------------------------------------------
// s1 = z1 @ W_fc[:, :HD]^T, split-K 16 slices of 128.
// ---------------------------------------------------------------------------
__global__ __launch_bounds__(256, 2) void s1_kernel(
    const float* __restrict__ A, const float* __restrict__ W)
{
    __shared__ float As[16][132];
    __shared__ float Bs[16][68];

    const int tid   = threadIdx.x;
    const int cg    = tid & 15;
    const int rg    = tid >> 4;
    const int row0  = blockIdx.x * 128;
    const int kbase = blockIdx.y * 128;

    const int lrow = tid >> 2;
    const int lq   = tid & 3;
    const float* Aptr0 = A + (size_t)(row0 + lrow) * HD + kbase + lq * 4;
    const float* Aptr1 = Aptr0 + (size_t)64 * HD;

    float acc[8][5];
    #pragma unroll
    for (int r = 0; r < 8; r++)
        #pragma unroll
        for (int j = 0; j < 5; j++) acc[r][j] = 0.f;

    for (int kk = 0; kk < 128; kk += 16) {
        __syncthreads();
        {
            float4 a0 = *(const float4*)(Aptr0 + kk);
            float4 a1 = *(const float4*)(Aptr1 + kk);
            As[lq*4+0][lrow]    = a0.x; As[lq*4+1][lrow]    = a0.y;
            As[lq*4+2][lrow]    = a0.z; As[lq*4+3][lrow]    = a0.w;
            As[lq*4+0][lrow+64] = a1.x; As[lq*4+1][lrow+64] = a1.y;
            As[lq*4+2][lrow+64] = a1.z; As[lq*4+3][lrow+64] = a1.w;
        }
        for (int f = tid; f < NC * 4; f += 256) {
            int n = f >> 2, q = f & 3;
            float4 w = *(const float4*)(W + (size_t)n * WLD + kbase + kk + q * 4);
            Bs[q*4+0][n] = w.x; Bs[q*4+1][n] = w.y;
            Bs[q*4+2][n] = w.z; Bs[q*4+3][n] = w.w;
        }
        __syncthreads();

        if (cg < 13) {
            #pragma unroll
            for (int k = 0; k < 16; k++) {
                float4 av0 = *(const float4*)(&As[k][rg*8]);
                float4 av1 = *(const float4*)(&As[k][rg*8+4]);
                float a[8] = {av0.x,av0.y,av0.z,av0.w,av1.x,av1.y,av1.z,av1.w};
                #pragma unroll
                for (int j = 0; j < 5; j++) {
                    float b = Bs[k][cg*5 + j];
                    #pragma unroll
                    for (int r = 0; r < 8; r++)
                        acc[r][j] += a[r] * b;
                }
            }
        }
    }

    if (cg < 13) {
        #pragma unroll
        for (int r = 0; r < 8; r++)
            #pragma unroll
            for (int j = 0; j < 5; j++)
                g_s1part[(size_t)blockIdx.y * (BSZ * NC)
                         + (size_t)(row0 + rg*8 + r) * NC + cg*5 + j] = acc[r][j];
    }
}

// out[i,c] = 2048 * s1[i,c] + g_T[c]
__global__ void out_kernel(float* __restrict__ out)
{
    int idx = blockIdx.x * 256 + threadIdx.x;
    if (idx < BSZ * NC) {
        int c = idx % NC;
        float s = 0.f;
        #pragma unroll
        for (int sl = 0; sl < KSPLIT; sl++) s += g_s1part[sl * (BSZ * NC) + idx];
        out[idx] = 2048.f * s + g_T[c];
    }
}

extern "C" void kernel_launch(void* const* d_in, const int* in_sizes, int n_in,
                              void* d_out, int out_size)
{
    const float* z1  = (const float*)d_in[0];
    const float* z2  = (const float*)d_in[1];
    const float* Wp  = (const float*)d_in[2];
    const float* bp  = (const float*)d_in[3];
    const float* Wfc = (const float*)d_in[4];
    const float* bfc = (const float*)d_in[5];
    float* out = (float*)d_out;

    cudaFuncSetAttribute(gemm1_tc, cudaFuncAttributeMaxDynamicSharedMemorySize, G1_SMEM);

    // Device addresses of __device__ globals
    __nv_bfloat16* Abf = nullptr;
    __nv_bfloat16* Bbf = nullptr;
    cudaGetSymbolAddress((void**)&Abf, g_Abf);
    cudaGetSymbolAddress((void**)&Bbf, g_Bbf);

    // Side stream + events, created once (no device memory involved).
    static cudaStream_t s_side = nullptr;
    static cudaEvent_t  ev_fork = nullptr, ev_join = nullptr;
    if (s_side == nullptr) {
        cudaStreamCreateWithFlags(&s_side, cudaStreamNonBlocking);
        cudaEventCreateWithFlags(&ev_fork, cudaEventDisableTiming);
        cudaEventCreateWithFlags(&ev_join, cudaEventDisableTiming);
    }

    // Fork: side stream inherits capture via event wait.
    cudaEventRecord(ev_fork, 0);
    cudaStreamWaitEvent(s_side, ev_fork, 0);

    // Side branch: s1 (fp32, SIMT)
    s1_kernel<<<dim3(16, KSPLIT), 256, 0, s_side>>>(z1, Wfc);
    cudaEventRecord(ev_join, s_side);

    // Main branch: convert -> gemm1 -> s2 (tensor/bandwidth chain)
    convert_kernel<<<1184, 512>>>(z2, Wp);
    gemm1_tc<<<128, 512, G1_SMEM>>>(Abf, Bbf, bp);
    s2_kernel<<<NC, 128>>>(Wfc, bfc);

    // Join, then combine.
    cudaStreamWaitEvent(0, ev_join, 0);
    out_kernel<<<(BSZ * NC + 255) / 256, 256>>>(out);
}

// round 9
// speedup vs baseline: 5.3445x; 1.1115x over previous
#include <cuda_runtime.h>
#include <cuda_bf16.h>
#include <cstdint>

// Problem constants
#define BSZ   2048
#define K1    9408     // 3*56*56
#define N1    1024     // PROJ_OUT
#define HD    2048     // HIDDEN_DIM
#define NC    65       // N_CLASSES
#define WLD   3072     // W_fc leading dim
#define KSPLIT 16      // s1 split-K slices

// ---------------------------------------------------------------------------
// PTX helpers (baseline ISA only)
// ---------------------------------------------------------------------------
__device__ __forceinline__ uint32_t smem_to_u32(const void* p) {
    uint32_t a;
    asm("{ .reg .u64 t; cvta.to.shared.u64 t, %1; cvt.u32.u64 %0, t; }" : "=r"(a) : "l"(p));
    return a;
}
#define CP_ASYNC_16(dst, src) \
    asm volatile("cp.async.cg.shared.global [%0], [%1], 16;" :: "r"(dst), "l"(src))
#define CP_ASYNC_COMMIT() asm volatile("cp.async.commit_group;" ::: "memory")
#define CP_ASYNC_WAIT(n)  asm volatile("cp.async.wait_group %0;" :: "n"(n) : "memory")

#define LDSM_X4(r0,r1,r2,r3,addr) \
    asm volatile("ldmatrix.sync.aligned.m8n8.x4.shared.b16 {%0,%1,%2,%3}, [%4];" \
        : "=r"(r0),"=r"(r1),"=r"(r2),"=r"(r3) : "r"(addr))

#define MMA_BF16(c0,c1,c2,c3,a0,a1,a2,a3,b0,b1) \
    asm volatile("mma.sync.aligned.m16n8k16.row.col.f32.bf16.bf16.f32 " \
        "{%0,%1,%2,%3}, {%4,%5,%6,%7}, {%8,%9}, {%0,%1,%2,%3};" \
        : "+f"(c0),"+f"(c1),"+f"(c2),"+f"(c3) \
        : "r"(a0),"r"(a1),"r"(a2),"r"(a3), "r"(b0),"r"(b1))

// ---------------------------------------------------------------------------
// Scratch (A is no longer pre-converted; only W_proj bf16)
// ---------------------------------------------------------------------------
__device__ __nv_bfloat16 g_Bbf[(size_t)N1 * K1];    // W_proj bf16 (19.3 MB, L2-resident)
__device__ float g_partial[16 * N1];                // per-M-block column sums
__device__ float g_T[NC];
__device__ float g_s1part[KSPLIT * BSZ * NC];

// ---------------------------------------------------------------------------
// fp32 -> bf16 conversion for B (W_proj) only.
// ---------------------------------------------------------------------------
#define NB4 ((N1 * K1) / 4)
__global__ void convertB_kernel(const float* __restrict__ srcB)
{
    int i = blockIdx.x * blockDim.x + threadIdx.x;
    const int stride = gridDim.x * blockDim.x;
    for (; i < NB4; i += stride) {
        float4 f = ((const float4*)srcB)[i];
        __nv_bfloat162 lo = __floats2bfloat162_rn(f.x, f.y);
        __nv_bfloat162 hi = __floats2bfloat162_rn(f.z, f.w);
        uint2 v;
        v.x = *(uint32_t*)&lo;
        v.y = *(uint32_t*)&hi;
        ((uint2*)g_Bbf)[i] = v;
    }
}

// ---------------------------------------------------------------------------
// GEMM1 fused: A read as fp32 from global (z2 directly), converted to bf16
// in registers, staged through a 2-buffer smem ring. B bf16 via cp.async
// (3 stages). CTA tile 128x128, BK=64, 16 warps (warp tile 32x32).
// relu(A@B^T + bias) reduced to column sums.
// ---------------------------------------------------------------------------
#define G1_ITERS   147                 // 9408 / 64
#define ROWB       144                 // 64 bf16 (128B) + 16B pad
#define TILE_B     (128 * ROWB)        // 18432 bytes per operand tile
#define A_OFF      0                   // A ring: 2 x TILE_B
#define B_OFF      (2 * TILE_B)        // B ring: 3 x TILE_B
#define SRED_OFF   (5 * TILE_B)        // 92160
#define G1_SMEM    (SRED_OFF + 16 * 32 * 4)

__global__ __launch_bounds__(512, 1) void gemm1_tc(
    const float* __restrict__ Ag, const __nv_bfloat16* __restrict__ Bg,
    const float* __restrict__ bias)
{
    extern __shared__ char smem[];
    const uint32_t sb = smem_to_u32(smem);
    const int tid  = threadIdx.x;
    const int lane = tid & 31;
    const int warp = tid >> 5;         // 0..15
    const int wm   = warp >> 2;        // 0..3  (M 32-row strip)
    const int wn   = warp & 3;         // 0..3  (N 32-col strip)
    const int mtile = blockIdx.x & 15;
    const int ntile = blockIdx.x >> 4;
    const int row0 = mtile * 128;
    const int col0 = ntile * 128;

    // B stage loader: 1024 chunks of 16B -> 2 per thread
    auto load_B = [&](int buf, int k0) {
        const uint32_t sB = sb + B_OFF + buf * TILE_B;
        #pragma unroll
        for (int i = 0; i < 2; i++) {
            const int v = tid + i * 512;     // 0..1023
            const int r = v >> 3, c = v & 7;
            CP_ASYNC_16(sB + r * ROWB + c * 16,
                        Bg + (size_t)(col0 + r) * K1 + k0 + c * 8);
        }
    };

    // A: 128 rows x 64 fp32 per stage = 2048 float4 -> 4 per thread
    float4 pre[4];
    auto ldg_A = [&](int k0) {
        #pragma unroll
        for (int i = 0; i < 4; i++) {
            const int v = tid + i * 512;
            const int r = v >> 4, c = v & 15;
            pre[i] = *(const float4*)(Ag + (size_t)(row0 + r) * K1 + k0 + c * 4);
        }
    };
    auto sts_A = [&](int buf) {
        #pragma unroll
        for (int i = 0; i < 4; i++) {
            const int v = tid + i * 512;
            const int r = v >> 4, c = v & 15;
            __nv_bfloat162 lo = __floats2bfloat162_rn(pre[i].x, pre[i].y);
            __nv_bfloat162 hi = __floats2bfloat162_rn(pre[i].z, pre[i].w);
            uint2 d;
            d.x = *(uint32_t*)&lo;
            d.y = *(uint32_t*)&hi;
            *(uint2*)(smem + A_OFF + buf * TILE_B + r * ROWB + c * 8) = d;
        }
    };

    float acc[2][4][4];
    #pragma unroll
    for (int mt = 0; mt < 2; mt++)
        #pragma unroll
        for (int nt = 0; nt < 4; nt++)
            #pragma unroll
            for (int q = 0; q < 4; q++) acc[mt][nt][q] = 0.f;

    // Prologue: A stage 0 (reg->cvt->smem), prefetch A stage 1 regs; B stages 0,1.
    ldg_A(0);
    load_B(0, 0);  CP_ASYNC_COMMIT();
    load_B(1, 64); CP_ASYNC_COMMIT();
    sts_A(0);
    ldg_A(64);
    CP_ASYNC_WAIT(1);
    __syncthreads();

    const int lrow = lane & 15;
    const int lseg = lane >> 4;

    int bbuf = 0;
    #pragma unroll 1
    for (int it = 0; it < G1_ITERS; it++) {
        const uint32_t sa = sb + A_OFF + (it & 1) * TILE_B;
        const uint32_t sB = sb + B_OFF + bbuf * TILE_B;

        if (it + 2 < G1_ITERS) {
            int nb = bbuf + 2; if (nb >= 3) nb -= 3;
            load_B(nb, (it + 2) * 64);
        }
        CP_ASYNC_COMMIT();

        #pragma unroll
        for (int ks = 0; ks < 4; ks++) {
            const uint32_t koff = ks * 32 + lseg * 16;
            uint32_t a[2][4];
            #pragma unroll
            for (int mt = 0; mt < 2; mt++) {
                uint32_t ad = sa + (uint32_t)(wm * 32 + mt * 16 + lrow) * ROWB + koff;
                LDSM_X4(a[mt][0], a[mt][1], a[mt][2], a[mt][3], ad);
            }
            uint32_t bfr[2][4];
            #pragma unroll
            for (int nb2 = 0; nb2 < 2; nb2++) {
                uint32_t bd = sB + (uint32_t)(wn * 32 + nb2 * 16 + lrow) * ROWB + koff;
                LDSM_X4(bfr[nb2][0], bfr[nb2][1], bfr[nb2][2], bfr[nb2][3], bd);
            }
            #pragma unroll
            for (int mt = 0; mt < 2; mt++)
                #pragma unroll
                for (int nt = 0; nt < 4; nt++) {
                    const int nb2 = nt >> 1, rs = nt & 1;
                    MMA_BF16(acc[mt][nt][0], acc[mt][nt][1], acc[mt][nt][2], acc[mt][nt][3],
                             a[mt][0], a[mt][1], a[mt][2], a[mt][3],
                             bfr[nb2][rs], bfr[nb2][rs + 2]);
                }
        }

        // Store prefetched A regs into next A buffer; prefetch the one after.
        if (it + 1 < G1_ITERS) sts_A((it + 1) & 1);
        if (it + 2 < G1_ITERS) ldg_A((it + 2) * 64);

        CP_ASYNC_WAIT(1);
        __syncthreads();
        bbuf++; if (bbuf >= 3) bbuf = 0;
    }

    // Epilogue: bias + relu, column sums over the CTA's 128 rows.
    float* sred = (float*)(smem + SRED_OFF);    // [16 warps][32 cols]
    #pragma unroll
    for (int nt = 0; nt < 4; nt++) {
        #pragma unroll
        for (int j = 0; j < 2; j++) {
            const int colL = nt * 8 + (lane & 3) * 2 + j;
            const float bb = bias[col0 + wn * 32 + colL];
            float s = 0.f;
            #pragma unroll
            for (int mt = 0; mt < 2; mt++)
                s += fmaxf(acc[mt][nt][j] + bb, 0.f) + fmaxf(acc[mt][nt][j + 2] + bb, 0.f);
            s += __shfl_down_sync(0xffffffffu, s, 16);
            s += __shfl_down_sync(0xffffffffu, s, 8);
            s += __shfl_down_sync(0xffffffffu, s, 4);
            if ((lane >> 2) == 0) sred[warp * 32 + colL] = s;
        }
    }
    __syncthreads();
    if (tid < 128) {
        const int wnq = tid >> 5, cl = tid & 31;
        float s = 0.f;
        #pragma unroll
        for (int wmq = 0; wmq < 4; wmq++)
            s += sred[(wmq * 4 + wnq) * 32 + cl];
        g_partial[mtile * N1 + col0 + tid] = s;
    }
}

// g_T[c] = (Σ_m g_partial[m]) . W_fc[c, HD:] + 2048*b_fc[c]   (u on the fly)
__global__ void s2_kernel(const float* __restrict__ Wfc, const float* __restrict__ bfc)
{
    __shared__ float red[128];
    const int c = blockIdx.x, tid = threadIdx.x;
    const float* w = Wfc + (size_t)c * WLD + HD;
    float p = 0.f;
    for (int k = tid; k < N1; k += 128) {
        float u = 0.f;
        #pragma unroll
        for (int m = 0; m < 16; m++) u += g_partial[m * N1 + k];
        p += u * w[k];
    }
    red[tid] = p;
    __syncthreads();
    for (int s = 64; s > 0; s >>= 1) {
        if (tid < s) red[tid] += red[tid + s];
        __syncthreads();
    }
    if (tid == 0) g_T[c] = red[0] + 2048.f * bfc[c];
}

// ---------------------------------------------------------------------------
// s1 = z1 @ W_fc[:, :HD]^T, split-K 16 slices of 128.
// ---------------------------------------------------------------------------
__global__ __launch_bounds__(256, 2) void s1_kernel(
    const float* __restrict__ A, const float* __restrict__ W)
{
    __shared__ float As[16][132];
    __shared__ float Bs[16][68];

    const int tid   = threadIdx.x;
    const int cg    = tid & 15;
    const int rg    = tid >> 4;
    const int row0  = blockIdx.x * 128;
    const int kbase = blockIdx.y * 128;

    const int lrow = tid >> 2;
    const int lq   = tid & 3;
    const float* Aptr0 = A + (size_t)(row0 + lrow) * HD + kbase + lq * 4;
    const float* Aptr1 = Aptr0 + (size_t)64 * HD;

    float acc[8][5];
    #pragma unroll
    for (int r = 0; r < 8; r++)
        #pragma unroll
        for (int j = 0; j < 5; j++) acc[r][j] = 0.f;

    for (int kk = 0; kk < 128; kk += 16) {
        __syncthreads();
        {
            float4 a0 = *(const float4*)(Aptr0 + kk);
            float4 a1 = *(const float4*)(Aptr1 + kk);
            As[lq*4+0][lrow]    = a0.x; As[lq*4+1][lrow]    = a0.y;
            As[lq*4+2][lrow]    = a0.z; As[lq*4+3][lrow]    = a0.w;
            As[lq*4+0][lrow+64] = a1.x; As[lq*4+1][lrow+64] = a1.y;
            As[lq*4+2][lrow+64] = a1.z; As[lq*4+3][lrow+64] = a1.w;
        }
        for (int f = tid; f < NC * 4; f += 256) {
            int n = f >> 2, q = f & 3;
            float4 w = *(const float4*)(W + (size_t)n * WLD + kbase + kk + q * 4);
            Bs[q*4+0][n] = w.x; Bs[q*4+1][n] = w.y;
            Bs[q*4+2][n] = w.z; Bs[q*4+3][n] = w.w;
        }
        __syncthreads();

        if (cg < 13) {
            #pragma unroll
            for (int k = 0; k < 16; k++) {
                float4 av0 = *(const float4*)(&As[k][rg*8]);
                float4 av1 = *(const float4*)(&As[k][rg*8+4]);
                float a[8] = {av0.x,av0.y,av0.z,av0.w,av1.x,av1.y,av1.z,av1.w};
                #pragma unroll
                for (int j = 0; j < 5; j++) {
                    float b = Bs[k][cg*5 + j];
                    #pragma unroll
                    for (int r = 0; r < 8; r++)
                        acc[r][j] += a[r] * b;
                }
            }
        }
    }

    if (cg < 13) {
        #pragma unroll
        for (int r = 0; r < 8; r++)
            #pragma unroll
            for (int j = 0; j < 5; j++)
                g_s1part[(size_t)blockIdx.y * (BSZ * NC)
                         + (size_t)(row0 + rg*8 + r) * NC + cg*5 + j] = acc[r][j];
    }
}

// out[i,c] = 2048 * s1[i,c] + g_T[c]
__global__ void out_kernel(float* __restrict__ out)
{
    int idx = blockIdx.x * 256 + threadIdx.x;
    if (idx < BSZ * NC) {
        int c = idx % NC;
        float s = 0.f;
        #pragma unroll
        for (int sl = 0; sl < KSPLIT; sl++) s += g_s1part[sl * (BSZ * NC) + idx];
        out[idx] = 2048.f * s + g_T[c];
    }
}

extern "C" void kernel_launch(void* const* d_in, const int* in_sizes, int n_in,
                              void* d_out, int out_size)
{
    const float* z1  = (const float*)d_in[0];
    const float* z2  = (const float*)d_in[1];
    const float* Wp  = (const float*)d_in[2];
    const float* bp  = (const float*)d_in[3];
    const float* Wfc = (const float*)d_in[4];
    const float* bfc = (const float*)d_in[5];
    float* out = (float*)d_out;

    cudaFuncSetAttribute(gemm1_tc, cudaFuncAttributeMaxDynamicSharedMemorySize, G1_SMEM);

    __nv_bfloat16* Bbf = nullptr;
    cudaGetSymbolAddress((void**)&Bbf, g_Bbf);

    // Side stream + events, created once (no device memory involved).
    static cudaStream_t s_side = nullptr;
    static cudaEvent_t  ev_fork = nullptr, ev_join = nullptr;
    if (s_side == nullptr) {
        cudaStreamCreateWithFlags(&s_side, cudaStreamNonBlocking);
        cudaEventCreateWithFlags(&ev_fork, cudaEventDisableTiming);
        cudaEventCreateWithFlags(&ev_join, cudaEventDisableTiming);
    }

    // Fork: side stream inherits capture via event wait.
    cudaEventRecord(ev_fork, 0);
    cudaStreamWaitEvent(s_side, ev_fork, 0);

    // Side branch: s1 (fp32, SIMT) — overlaps the compute-bound gemm chain.
    s1_kernel<<<dim3(16, KSPLIT), 256, 0, s_side>>>(z1, Wfc);
    cudaEventRecord(ev_join, s_side);

    // Main branch: convert B (small) -> fused gemm1 (A converted in-kernel) -> s2
    convertB_kernel<<<592, 512>>>(Wp);
    gemm1_tc<<<128, 512, G1_SMEM>>>(z2, Bbf, bp);
    s2_kernel<<<NC, 128>>>(Wfc, bfc);

    // Join, then combine.
    cudaStreamWaitEvent(0, ev_join, 0);
    out_kernel<<<(BSZ * NC + 255) / 256, 256>>>(out);
}

// round 11
// speedup vs baseline: 5.4892x; 1.0271x over previous
#include <cuda_runtime.h>
#include <cuda_bf16.h>
#include <cstdint>

// Problem constants
#define BSZ   2048
#define K1    9408     // 3*56*56
#define N1    1024     // PROJ_OUT
#define HD    2048     // HIDDEN_DIM
#define NC    65       // N_CLASSES
#define WLD   3072     // W_fc leading dim
#define KSPLIT 16      // s1 split-K slices

// ---------------------------------------------------------------------------
// PTX helpers (baseline ISA only)
// ---------------------------------------------------------------------------
__device__ __forceinline__ uint32_t smem_to_u32(const void* p) {
    uint32_t a;
    asm("{ .reg .u64 t; cvta.to.shared.u64 t, %1; cvt.u32.u64 %0, t; }" : "=r"(a) : "l"(p));
    return a;
}
#define CP_ASYNC_16(dst, src) \
    asm volatile("cp.async.cg.shared.global [%0], [%1], 16;" :: "r"(dst), "l"(src))
#define CP_ASYNC_COMMIT() asm volatile("cp.async.commit_group;" ::: "memory")
#define CP_ASYNC_WAIT(n)  asm volatile("cp.async.wait_group %0;" :: "n"(n) : "memory")

#define LDSM_X4(r0,r1,r2,r3,addr) \
    asm volatile("ldmatrix.sync.aligned.m8n8.x4.shared.b16 {%0,%1,%2,%3}, [%4];" \
        : "=r"(r0),"=r"(r1),"=r"(r2),"=r"(r3) : "r"(addr))

#define MMA_BF16(c0,c1,c2,c3,a0,a1,a2,a3,b0,b1) \
    asm volatile("mma.sync.aligned.m16n8k16.row.col.f32.bf16.bf16.f32 " \
        "{%0,%1,%2,%3}, {%4,%5,%6,%7}, {%8,%9}, {%0,%1,%2,%3};" \
        : "+f"(c0),"+f"(c1),"+f"(c2),"+f"(c3) \
        : "r"(a0),"r"(a1),"r"(a2),"r"(a3), "r"(b0),"r"(b1))

// ---------------------------------------------------------------------------
// Scratch
// ---------------------------------------------------------------------------
__device__ __nv_bfloat16 g_Bbf[(size_t)N1 * K1];      // W_proj bf16 (19.3 MB)
__device__ float g_Dpart[(size_t)2 * BSZ * N1];       // raw K-half partials (16.8 MB)
__device__ float g_partial[32 * N1];                  // per row-block column sums
__device__ float g_T[NC];
__device__ float g_s1part[KSPLIT * BSZ * NC];

// ---------------------------------------------------------------------------
// fp32 -> bf16 conversion for B (W_proj) only.
// ---------------------------------------------------------------------------
#define NB4 ((N1 * K1) / 4)
__global__ void convertB_kernel(const float* __restrict__ srcB)
{
    int i = blockIdx.x * blockDim.x + threadIdx.x;
    const int stride = gridDim.x * blockDim.x;
    for (; i < NB4; i += stride) {
        float4 f = ((const float4*)srcB)[i];
        __nv_bfloat162 lo = __floats2bfloat162_rn(f.x, f.y);
        __nv_bfloat162 hi = __floats2bfloat162_rn(f.z, f.w);
        uint2 v;
        v.x = *(uint32_t*)&lo;
        v.y = *(uint32_t*)&hi;
        ((uint2*)g_Bbf)[i] = v;
    }
}

// ---------------------------------------------------------------------------
// GEMM1 fused: CTA tile 128M x 256N, K split in 2 halves (grid 16x4x2 = 128).
// A read fp32 from z2, cvt->bf16 in regs, 2-buffer smem ring. B bf16 via
// cp.async 3-stage ring. 16 warps, warp tile 32x64.
// Epilogue stores RAW fp32 partial tiles (relu is applied only after both
// K-halves are summed, in relu_colsum_kernel — relu is nonlinear!).
// ---------------------------------------------------------------------------
#define ROWB       144                 // 64 bf16 (128B) + 16B pad
#define A_TILE     (128 * ROWB)        // 18432
#define B_TILE     (256 * ROWB)        // 36864
#define A_OFF      0                   // A ring: 2 x A_TILE
#define B_OFF      (2 * A_TILE)        // B ring: 3 x B_TILE
#define G1_SMEM    (B_OFF + 3 * B_TILE)   // 147456

__global__ __launch_bounds__(512, 1) void gemm1_tc(
    const float* __restrict__ Ag, const __nv_bfloat16* __restrict__ Bg)
{
    extern __shared__ char smem[];
    const uint32_t sb = smem_to_u32(smem);
    const int tid  = threadIdx.x;
    const int lane = tid & 31;
    const int warp = tid >> 5;         // 0..15
    const int wm   = warp >> 2;        // 0..3  (M 32-row strip)
    const int wn   = warp & 3;         // 0..3  (N 64-col strip)
    const int mtile = blockIdx.x & 15;
    const int rest  = blockIdx.x >> 4;
    const int ntile = rest & 3;
    const int khalf = rest >> 2;
    const int row0 = mtile * 128;
    const int col0 = ntile * 256;
    const int kbase = khalf ? 4736 : 0;        // 74*64
    const int iters = khalf ? 73 : 74;

    // B stage loader: 256 rows x 8 chunks = 2048 chunks of 16B -> 4/thread
    auto load_B = [&](int buf, int k0) {
        const uint32_t sB = sb + B_OFF + buf * B_TILE;
        #pragma unroll
        for (int i = 0; i < 4; i++) {
            const int v = tid + i * 512;     // 0..2047
            const int r = v >> 3, c = v & 7;
            CP_ASYNC_16(sB + r * ROWB + c * 16,
                        Bg + (size_t)(col0 + r) * K1 + k0 + c * 8);
        }
    };

    // A: 128 rows x 64 fp32 per stage = 2048 float4 -> 4/thread
    float4 pre[4];
    auto ldg_A = [&](int k0) {
        #pragma unroll
        for (int i = 0; i < 4; i++) {
            const int v = tid + i * 512;
            const int r = v >> 4, c = v & 15;
            pre[i] = *(const float4*)(Ag + (size_t)(row0 + r) * K1 + k0 + c * 4);
        }
    };
    auto sts_A = [&](int buf) {
        #pragma unroll
        for (int i = 0; i < 4; i++) {
            const int v = tid + i * 512;
            const int r = v >> 4, c = v & 15;
            __nv_bfloat162 lo = __floats2bfloat162_rn(pre[i].x, pre[i].y);
            __nv_bfloat162 hi = __floats2bfloat162_rn(pre[i].z, pre[i].w);
            uint2 d;
            d.x = *(uint32_t*)&lo;
            d.y = *(uint32_t*)&hi;
            *(uint2*)(smem + A_OFF + buf * A_TILE + r * ROWB + c * 8) = d;
        }
    };

    float acc[2][8][4];
    #pragma unroll
    for (int mt = 0; mt < 2; mt++)
        #pragma unroll
        for (int nt = 0; nt < 8; nt++)
            #pragma unroll
            for (int q = 0; q < 4; q++) acc[mt][nt][q] = 0.f;

    // Prologue
    ldg_A(kbase);
    load_B(0, kbase);      CP_ASYNC_COMMIT();
    load_B(1, kbase + 64); CP_ASYNC_COMMIT();
    sts_A(0);
    ldg_A(kbase + 64);
    CP_ASYNC_WAIT(1);
    __syncthreads();

    const int lrow = lane & 15;
    const int lseg = lane >> 4;

    int bbuf = 0;
    #pragma unroll 1
    for (int it = 0; it < iters; it++) {
        const uint32_t sa = sb + A_OFF + (it & 1) * A_TILE;
        const uint32_t sB = sb + B_OFF + bbuf * B_TILE;

        if (it + 2 < iters) {
            int nb = bbuf + 2; if (nb >= 3) nb -= 3;
            load_B(nb, kbase + (it + 2) * 64);
        }
        CP_ASYNC_COMMIT();

        #pragma unroll
        for (int ks = 0; ks < 4; ks++) {
            const uint32_t koff = ks * 32 + lseg * 16;
            uint32_t a[2][4];
            #pragma unroll
            for (int mt = 0; mt < 2; mt++) {
                uint32_t ad = sa + (uint32_t)(wm * 32 + mt * 16 + lrow) * ROWB + koff;
                LDSM_X4(a[mt][0], a[mt][1], a[mt][2], a[mt][3], ad);
            }
            uint32_t bfr[4][4];
            #pragma unroll
            for (int nb2 = 0; nb2 < 4; nb2++) {
                uint32_t bd = sB + (uint32_t)(wn * 64 + nb2 * 16 + lrow) * ROWB + koff;
                LDSM_X4(bfr[nb2][0], bfr[nb2][1], bfr[nb2][2], bfr[nb2][3], bd);
            }
            #pragma unroll
            for (int mt = 0; mt < 2; mt++)
                #pragma unroll
                for (int nt = 0; nt < 8; nt++) {
                    const int nb2 = nt >> 1, rs = nt & 1;
                    MMA_BF16(acc[mt][nt][0], acc[mt][nt][1], acc[mt][nt][2], acc[mt][nt][3],
                             a[mt][0], a[mt][1], a[mt][2], a[mt][3],
                             bfr[nb2][rs], bfr[nb2][rs + 2]);
                }
        }

        if (it + 1 < iters) sts_A((it + 1) & 1);
        if (it + 2 < iters) ldg_A(kbase + (it + 2) * 64);

        CP_ASYNC_WAIT(1);
        __syncthreads();
        bbuf++; if (bbuf >= 3) bbuf = 0;
    }

    // Epilogue: store raw fp32 partials. acc regs: [0]=(r,c) [1]=(r,c+1)
    // [2]=(r+8,c) [3]=(r+8,c+1); r=lane/4, c=(lane%4)*2.
    {
        float* Dp = g_Dpart + (size_t)khalf * BSZ * N1;
        const int rbase = row0 + wm * 32 + (lane >> 2);
        const int cbase = col0 + wn * 64 + (lane & 3) * 2;
        #pragma unroll
        for (int mt = 0; mt < 2; mt++)
            #pragma unroll
            for (int nt = 0; nt < 8; nt++) {
                const int r = rbase + mt * 16;
                const int c = cbase + nt * 8;
                *(float2*)(Dp + (size_t)r * N1 + c)       = make_float2(acc[mt][nt][0], acc[mt][nt][1]);
                *(float2*)(Dp + (size_t)(r + 8) * N1 + c) = make_float2(acc[mt][nt][2], acc[mt][nt][3]);
            }
    }
}

// relu(D0 + D1 + bias) column sums. Grid (32 row-blocks x 4 col-blocks), 256 thr.
__global__ void relu_colsum_kernel(const float* __restrict__ bias)
{
    const int bm = blockIdx.x & 31;        // 64-row block
    const int bn = blockIdx.x >> 5;        // 256-col block
    const int c  = bn * 256 + threadIdx.x;
    const float bb = bias[c];
    const float* p0 = g_Dpart + (size_t)(bm * 64) * N1 + c;
    const float* p1 = p0 + (size_t)BSZ * N1;
    float s = 0.f;
    #pragma unroll 4
    for (int r = 0; r < 64; r++)
        s += fmaxf(p0[(size_t)r * N1] + p1[(size_t)r * N1] + bb, 0.f);
    g_partial[bm * N1 + c] = s;
}

// g_T[c] = (Σ_m g_partial[m]) . W_fc[c, HD:] + 2048*b_fc[c]
__global__ void s2_kernel(const float* __restrict__ Wfc, const float* __restrict__ bfc)
{
    __shared__ float red[1024];
    const int c = blockIdx.x, tid = threadIdx.x;
    float u = 0.f;
    #pragma unroll
    for (int m = 0; m < 32; m++) u += g_partial[m * N1 + tid];
    red[tid] = u * Wfc[(size_t)c * WLD + HD + tid];
    __syncthreads();
    for (int s = 512; s > 0; s >>= 1) {
        if (tid < s) red[tid] += red[tid + s];
        __syncthreads();
    }
    if (tid == 0) g_T[c] = red[0] + 2048.f * bfc[c];
}

// ---------------------------------------------------------------------------
// s1 = z1 @ W_fc[:, :HD]^T, split-K 16 slices of 128.
// ---------------------------------------------------------------------------
__global__ __launch_bounds__(256, 2) void s1_kernel(
    const float* __restrict__ A, const float* __restrict__ W)
{
    __shared__ float As[16][132];
    __shared__ float Bs[16][68];

    const int tid   = threadIdx.x;
    const int cg    = tid & 15;
    const int rg    = tid >> 4;
    const int row0  = blockIdx.x * 128;
    const int kbase = blockIdx.y * 128;

    const int lrow = tid >> 2;
    const int lq   = tid & 3;
    const float* Aptr0 = A + (size_t)(row0 + lrow) * HD + kbase + lq * 4;
    const float* Aptr1 = Aptr0 + (size_t)64 * HD;

    float acc[8][5];
    #pragma unroll
    for (int r = 0; r < 8; r++)
        #pragma unroll
        for (int j = 0; j < 5; j++) acc[r][j] = 0.f;

    for (int kk = 0; kk < 128; kk += 16) {
        __syncthreads();
        {
            float4 a0 = *(const float4*)(Aptr0 + kk);
            float4 a1 = *(const float4*)(Aptr1 + kk);
            As[lq*4+0][lrow]    = a0.x; As[lq*4+1][lrow]    = a0.y;
            As[lq*4+2][lrow]    = a0.z; As[lq*4+3][lrow]    = a0.w;
            As[lq*4+0][lrow+64] = a1.x; As[lq*4+1][lrow+64] = a1.y;
            As[lq*4+2][lrow+64] = a1.z; As[lq*4+3][lrow+64] = a1.w;
        }
        for (int f = tid; f < NC * 4; f += 256) {
            int n = f >> 2, q = f & 3;
            float4 w = *(const float4*)(W + (size_t)n * WLD + kbase + kk + q * 4);
            Bs[q*4+0][n] = w.x; Bs[q*4+1][n] = w.y;
            Bs[q*4+2][n] = w.z; Bs[q*4+3][n] = w.w;
        }
        __syncthreads();

        if (cg < 13) {
            #pragma unroll
            for (int k = 0; k < 16; k++) {
                float4 av0 = *(const float4*)(&As[k][rg*8]);
                float4 av1 = *(const float4*)(&As[k][rg*8+4]);
                float a[8] = {av0.x,av0.y,av0.z,av0.w,av1.x,av1.y,av1.z,av1.w};
                #pragma unroll
                for (int j = 0; j < 5; j++) {
                    float b = Bs[k][cg*5 + j];
                    #pragma unroll
                    for (int r = 0; r < 8; r++)
                        acc[r][j] += a[r] * b;
                }
            }
        }
    }

    if (cg < 13) {
        #pragma unroll
        for (int r = 0; r < 8; r++)
            #pragma unroll
            for (int j = 0; j < 5; j++)
                g_s1part[(size_t)blockIdx.y * (BSZ * NC)
                         + (size_t)(row0 + rg*8 + r) * NC + cg*5 + j] = acc[r][j];
    }
}

// out[i,c] = 2048 * s1[i,c] + g_T[c]
__global__ void out_kernel(float* __restrict__ out)
{
    int idx = blockIdx.x * 256 + threadIdx.x;
    if (idx < BSZ * NC) {
        int c = idx % NC;
        float s = 0.f;
        #pragma unroll
        for (int sl = 0; sl < KSPLIT; sl++) s += g_s1part[sl * (BSZ * NC) + idx];
        out[idx] = 2048.f * s + g_T[c];
    }
}

extern "C" void kernel_launch(void* const* d_in, const int* in_sizes, int n_in,
                              void* d_out, int out_size)
{
    const float* z1  = (const float*)d_in[0];
    const float* z2  = (const float*)d_in[1];
    const float* Wp  = (const float*)d_in[2];
    const float* bp  = (const float*)d_in[3];
    const float* Wfc = (const float*)d_in[4];
    const float* bfc = (const float*)d_in[5];
    float* out = (float*)d_out;

    cudaFuncSetAttribute(gemm1_tc, cudaFuncAttributeMaxDynamicSharedMemorySize, G1_SMEM);

    __nv_bfloat16* Bbf = nullptr;
    cudaGetSymbolAddress((void**)&Bbf, g_Bbf);

    // Side stream + events, created once (no device memory involved).
    static cudaStream_t s_side = nullptr;
    static cudaEvent_t  ev_fork = nullptr, ev_join = nullptr;
    if (s_side == nullptr) {
        cudaStreamCreateWithFlags(&s_side, cudaStreamNonBlocking);
        cudaEventCreateWithFlags(&ev_fork, cudaEventDisableTiming);
        cudaEventCreateWithFlags(&ev_join, cudaEventDisableTiming);
    }

    // Fork: side stream inherits capture via event wait.
    cudaEventRecord(ev_fork, 0);
    cudaStreamWaitEvent(s_side, ev_fork, 0);

    // Side branch: s1 (fp32, SIMT) — overlaps the compute-bound gemm chain.
    s1_kernel<<<dim3(16, KSPLIT), 256, 0, s_side>>>(z1, Wfc);
    cudaEventRecord(ev_join, s_side);

    // Main branch: convert B -> fused gemm1 (raw partials) -> relu+colsum -> s2
    convertB_kernel<<<592, 512>>>(Wp);
    gemm1_tc<<<128, 512, G1_SMEM>>>(z2, Bbf);
    relu_colsum_kernel<<<128, 256>>>(bp);
    s2_kernel<<<NC, 1024>>>(Wfc, bfc);

    // Join, then combine.
    cudaStreamWaitEvent(0, ev_join, 0);
    out_kernel<<<(BSZ * NC + 255) / 256, 256>>>(out);
}

// round 12
// speedup vs baseline: 5.5983x; 1.0199x over previous
#include <cuda_runtime.h>
#include <cuda_bf16.h>
#include <cstdint>

// Problem constants
#define BSZ   2048
#define K1    9408     // 3*56*56
#define N1    1024     // PROJ_OUT
#define HD    2048     // HIDDEN_DIM
#define NC    65       // N_CLASSES
#define WLD   3072     // W_fc leading dim
#define KSPLIT 16      // s1 split-K slices

// ---------------------------------------------------------------------------
// PTX helpers (baseline ISA only)
// ---------------------------------------------------------------------------
__device__ __forceinline__ uint32_t smem_to_u32(const void* p) {
    uint32_t a;
    asm("{ .reg .u64 t; cvta.to.shared.u64 t, %1; cvt.u32.u64 %0, t; }" : "=r"(a) : "l"(p));
    return a;
}
#define CP_ASYNC_16(dst, src) \
    asm volatile("cp.async.cg.shared.global [%0], [%1], 16;" :: "r"(dst), "l"(src))
#define CP_ASYNC_COMMIT() asm volatile("cp.async.commit_group;" ::: "memory")
#define CP_ASYNC_WAIT(n)  asm volatile("cp.async.wait_group %0;" :: "n"(n) : "memory")

#define LDSM_X4(r0,r1,r2,r3,addr) \
    asm volatile("ldmatrix.sync.aligned.m8n8.x4.shared.b16 {%0,%1,%2,%3}, [%4];" \
        : "=r"(r0),"=r"(r1),"=r"(r2),"=r"(r3) : "r"(addr))

#define MMA_BF16(c0,c1,c2,c3,a0,a1,a2,a3,b0,b1) \
    asm volatile("mma.sync.aligned.m16n8k16.row.col.f32.bf16.bf16.f32 " \
        "{%0,%1,%2,%3}, {%4,%5,%6,%7}, {%8,%9}, {%0,%1,%2,%3};" \
        : "+f"(c0),"+f"(c1),"+f"(c2),"+f"(c3) \
        : "r"(a0),"r"(a1),"r"(a2),"r"(a3), "r"(b0),"r"(b1))

// ---------------------------------------------------------------------------
// Scratch
// ---------------------------------------------------------------------------
__device__ __nv_bfloat16 g_Bbf[(size_t)N1 * K1];      // W_proj bf16 (19.3 MB)
__device__ __nv_bfloat16 g_Dbf[(size_t)2 * BSZ * N1]; // K-half partials bf16 (8.4 MB)
__device__ float g_partial[128 * N1];                 // per row-block column sums
__device__ float g_T[NC];
__device__ float g_s1part[KSPLIT * BSZ * NC];

// ---------------------------------------------------------------------------
// fp32 -> bf16 conversion for B (W_proj) only.
// ---------------------------------------------------------------------------
#define NB4 ((N1 * K1) / 4)
__global__ void convertB_kernel(const float* __restrict__ srcB)
{
    int i = blockIdx.x * blockDim.x + threadIdx.x;
    const int stride = gridDim.x * blockDim.x;
    for (; i < NB4; i += stride) {
        float4 f = ((const float4*)srcB)[i];
        __nv_bfloat162 lo = __floats2bfloat162_rn(f.x, f.y);
        __nv_bfloat162 hi = __floats2bfloat162_rn(f.z, f.w);
        uint2 v;
        v.x = *(uint32_t*)&lo;
        v.y = *(uint32_t*)&hi;
        ((uint2*)g_Bbf)[i] = v;
    }
}

// ---------------------------------------------------------------------------
// GEMM1 fused: CTA tile 128M x 256N, K split in 2 halves (grid 16x4x2 = 128).
// A read fp32 from z2, cvt->bf16 in regs, 2-buffer smem ring. B bf16 via
// cp.async 3-stage ring. 16 warps, warp tile 32x64.
// Epilogue stores raw partial tiles in bf16 (relu applied after the two
// K-halves are summed, in relu_colsum_kernel — relu is nonlinear).
// ---------------------------------------------------------------------------
#define ROWB       144                 // 64 bf16 (128B) + 16B pad
#define A_TILE     (128 * ROWB)        // 18432
#define B_TILE     (256 * ROWB)        // 36864
#define A_OFF      0                   // A ring: 2 x A_TILE
#define B_OFF      (2 * A_TILE)        // B ring: 3 x B_TILE
#define G1_SMEM    (B_OFF + 3 * B_TILE)   // 147456

__global__ __launch_bounds__(512, 1) void gemm1_tc(
    const float* __restrict__ Ag, const __nv_bfloat16* __restrict__ Bg)
{
    extern __shared__ char smem[];
    const uint32_t sb = smem_to_u32(smem);
    const int tid  = threadIdx.x;
    const int lane = tid & 31;
    const int warp = tid >> 5;         // 0..15
    const int wm   = warp >> 2;        // 0..3  (M 32-row strip)
    const int wn   = warp & 3;         // 0..3  (N 64-col strip)
    const int mtile = blockIdx.x & 15;
    const int rest  = blockIdx.x >> 4;
    const int ntile = rest & 3;
    const int khalf = rest >> 2;
    const int row0 = mtile * 128;
    const int col0 = ntile * 256;
    const int kbase = khalf ? 4736 : 0;        // 74*64
    const int iters = khalf ? 73 : 74;

    // B stage loader: 256 rows x 8 chunks = 2048 chunks of 16B -> 4/thread
    auto load_B = [&](int buf, int k0) {
        const uint32_t sB = sb + B_OFF + buf * B_TILE;
        #pragma unroll
        for (int i = 0; i < 4; i++) {
            const int v = tid + i * 512;     // 0..2047
            const int r = v >> 3, c = v & 7;
            CP_ASYNC_16(sB + r * ROWB + c * 16,
                        Bg + (size_t)(col0 + r) * K1 + k0 + c * 8);
        }
    };

    // A: 128 rows x 64 fp32 per stage = 2048 float4 -> 4/thread
    float4 pre[4];
    auto ldg_A = [&](int k0) {
        #pragma unroll
        for (int i = 0; i < 4; i++) {
            const int v = tid + i * 512;
            const int r = v >> 4, c = v & 15;
            pre[i] = *(const float4*)(Ag + (size_t)(row0 + r) * K1 + k0 + c * 4);
        }
    };
    auto sts_A = [&](int buf) {
        #pragma unroll
        for (int i = 0; i < 4; i++) {
            const int v = tid + i * 512;
            const int r = v >> 4, c = v & 15;
            __nv_bfloat162 lo = __floats2bfloat162_rn(pre[i].x, pre[i].y);
            __nv_bfloat162 hi = __floats2bfloat162_rn(pre[i].z, pre[i].w);
            uint2 d;
            d.x = *(uint32_t*)&lo;
            d.y = *(uint32_t*)&hi;
            *(uint2*)(smem + A_OFF + buf * A_TILE + r * ROWB + c * 8) = d;
        }
    };

    float acc[2][8][4];
    #pragma unroll
    for (int mt = 0; mt < 2; mt++)
        #pragma unroll
        for (int nt = 0; nt < 8; nt++)
            #pragma unroll
            for (int q = 0; q < 4; q++) acc[mt][nt][q] = 0.f;

    // Prologue
    ldg_A(kbase);
    load_B(0, kbase);      CP_ASYNC_COMMIT();
    load_B(1, kbase + 64); CP_ASYNC_COMMIT();
    sts_A(0);
    ldg_A(kbase + 64);
    CP_ASYNC_WAIT(1);
    __syncthreads();

    const int lrow = lane & 15;
    const int lseg = lane >> 4;

    int bbuf = 0;
    #pragma unroll 1
    for (int it = 0; it < iters; it++) {
        const uint32_t sa = sb + A_OFF + (it & 1) * A_TILE;
        const uint32_t sB = sb + B_OFF + bbuf * B_TILE;

        if (it + 2 < iters) {
            int nb = bbuf + 2; if (nb >= 3) nb -= 3;
            load_B(nb, kbase + (it + 2) * 64);
        }
        CP_ASYNC_COMMIT();

        #pragma unroll
        for (int ks = 0; ks < 4; ks++) {
            const uint32_t koff = ks * 32 + lseg * 16;
            uint32_t a[2][4];
            #pragma unroll
            for (int mt = 0; mt < 2; mt++) {
                uint32_t ad = sa + (uint32_t)(wm * 32 + mt * 16 + lrow) * ROWB + koff;
                LDSM_X4(a[mt][0], a[mt][1], a[mt][2], a[mt][3], ad);
            }
            uint32_t bfr[4][4];
            #pragma unroll
            for (int nb2 = 0; nb2 < 4; nb2++) {
                uint32_t bd = sB + (uint32_t)(wn * 64 + nb2 * 16 + lrow) * ROWB + koff;
                LDSM_X4(bfr[nb2][0], bfr[nb2][1], bfr[nb2][2], bfr[nb2][3], bd);
            }
            #pragma unroll
            for (int mt = 0; mt < 2; mt++)
                #pragma unroll
                for (int nt = 0; nt < 8; nt++) {
                    const int nb2 = nt >> 1, rs = nt & 1;
                    MMA_BF16(acc[mt][nt][0], acc[mt][nt][1], acc[mt][nt][2], acc[mt][nt][3],
                             a[mt][0], a[mt][1], a[mt][2], a[mt][3],
                             bfr[nb2][rs], bfr[nb2][rs + 2]);
                }
        }

        if (it + 1 < iters) sts_A((it + 1) & 1);
        if (it + 2 < iters) ldg_A(kbase + (it + 2) * 64);

        CP_ASYNC_WAIT(1);
        __syncthreads();
        bbuf++; if (bbuf >= 3) bbuf = 0;
    }

    // Epilogue: store raw bf16 partials. acc regs: [0]=(r,c) [1]=(r,c+1)
    // [2]=(r+8,c) [3]=(r+8,c+1); r=lane/4, c=(lane%4)*2 (c is even -> 4B aligned).
    {
        __nv_bfloat16* Dp = g_Dbf + (size_t)khalf * BSZ * N1;
        const int rbase = row0 + wm * 32 + (lane >> 2);
        const int cbase = col0 + wn * 64 + (lane & 3) * 2;
        #pragma unroll
        for (int mt = 0; mt < 2; mt++)
            #pragma unroll
            for (int nt = 0; nt < 8; nt++) {
                const int r = rbase + mt * 16;
                const int c = cbase + nt * 8;
                __nv_bfloat162 v0 = __floats2bfloat162_rn(acc[mt][nt][0], acc[mt][nt][1]);
                __nv_bfloat162 v1 = __floats2bfloat162_rn(acc[mt][nt][2], acc[mt][nt][3]);
                *(uint32_t*)(Dp + (size_t)r * N1 + c)       = *(uint32_t*)&v0;
                *(uint32_t*)(Dp + (size_t)(r + 8) * N1 + c) = *(uint32_t*)&v1;
            }
    }
}

// relu(D0 + D1 + bias) column sums. Grid (128 row-blocks x 4 col-blocks) = 512
// blocks, 256 thr, 16 rows per block -> good latency hiding (was 128 blocks).
__global__ void relu_colsum_kernel(const float* __restrict__ bias)
{
    const int bm = blockIdx.x & 127;       // 16-row block
    const int bn = blockIdx.x >> 7;        // 256-col block
    const int c  = bn * 256 + threadIdx.x;
    const float bb = bias[c];
    const __nv_bfloat16* p0 = g_Dbf + (size_t)(bm * 16) * N1 + c;
    const __nv_bfloat16* p1 = p0 + (size_t)BSZ * N1;
    float s = 0.f;
    #pragma unroll
    for (int r = 0; r < 16; r++)
        s += fmaxf(__bfloat162float(p0[(size_t)r * N1]) +
                   __bfloat162float(p1[(size_t)r * N1]) + bb, 0.f);
    g_partial[bm * N1 + c] = s;
}

// g_T[c] = (Σ_m g_partial[m]) . W_fc[c, HD:] + 2048*b_fc[c]
__global__ void s2_kernel(const float* __restrict__ Wfc, const float* __restrict__ bfc)
{
    __shared__ float red[1024];
    const int c = blockIdx.x, tid = threadIdx.x;
    float u = 0.f;
    #pragma unroll 8
    for (int m = 0; m < 128; m++) u += g_partial[m * N1 + tid];
    red[tid] = u * Wfc[(size_t)c * WLD + HD + tid];
    __syncthreads();
    for (int s = 512; s > 0; s >>= 1) {
        if (tid < s) red[tid] += red[tid + s];
        __syncthreads();
    }
    if (tid == 0) g_T[c] = red[0] + 2048.f * bfc[c];
}

// ---------------------------------------------------------------------------
// s1 = z1 @ W_fc[:, :HD]^T, split-K 16 slices of 128.
// ---------------------------------------------------------------------------
__global__ __launch_bounds__(256, 2) void s1_kernel(
    const float* __restrict__ A, const float* __restrict__ W)
{
    __shared__ float As[16][132];
    __shared__ float Bs[16][68];

    const int tid   = threadIdx.x;
    const int cg    = tid & 15;
    const int rg    = tid >> 4;
    const int row0  = blockIdx.x * 128;
    const int kbase = blockIdx.y * 128;

    const int lrow = tid >> 2;
    const int lq   = tid & 3;
    const float* Aptr0 = A + (size_t)(row0 + lrow) * HD + kbase + lq * 4;
    const float* Aptr1 = Aptr0 + (size_t)64 * HD;

    float acc[8][5];
    #pragma unroll
    for (int r = 0; r < 8; r++)
        #pragma unroll
        for (int j = 0; j < 5; j++) acc[r][j] = 0.f;

    for (int kk = 0; kk < 128; kk += 16) {
        __syncthreads();
        {
            float4 a0 = *(const float4*)(Aptr0 + kk);
            float4 a1 = *(const float4*)(Aptr1 + kk);
            As[lq*4+0][lrow]    = a0.x; As[lq*4+1][lrow]    = a0.y;
            As[lq*4+2][lrow]    = a0.z; As[lq*4+3][lrow]    = a0.w;
            As[lq*4+0][lrow+64] = a1.x; As[lq*4+1][lrow+64] = a1.y;
            As[lq*4+2][lrow+64] = a1.z; As[lq*4+3][lrow+64] = a1.w;
        }
        for (int f = tid; f < NC * 4; f += 256) {
            int n = f >> 2, q = f & 3;
            float4 w = *(const float4*)(W + (size_t)n * WLD + kbase + kk + q * 4);
            Bs[q*4+0][n] = w.x; Bs[q*4+1][n] = w.y;
            Bs[q*4+2][n] = w.z; Bs[q*4+3][n] = w.w;
        }
        __syncthreads();

        if (cg < 13) {
            #pragma unroll
            for (int k = 0; k < 16; k++) {
                float4 av0 = *(const float4*)(&As[k][rg*8]);
                float4 av1 = *(const float4*)(&As[k][rg*8+4]);
                float a[8] = {av0.x,av0.y,av0.z,av0.w,av1.x,av1.y,av1.z,av1.w};
                #pragma unroll
                for (int j = 0; j < 5; j++) {
                    float b = Bs[k][cg*5 + j];
                    #pragma unroll
                    for (int r = 0; r < 8; r++)
                        acc[r][j] += a[r] * b;
                }
            }
        }
    }

    if (cg < 13) {
        #pragma unroll
        for (int r = 0; r < 8; r++)
            #pragma unroll
            for (int j = 0; j < 5; j++)
                g_s1part[(size_t)blockIdx.y * (BSZ * NC)
                         + (size_t)(row0 + rg*8 + r) * NC + cg*5 + j] = acc[r][j];
    }
}

// out[i,c] = 2048 * s1[i,c] + g_T[c]
__global__ void out_kernel(float* __restrict__ out)
{
    int idx = blockIdx.x * 256 + threadIdx.x;
    if (idx < BSZ * NC) {
        int c = idx % NC;
        float s = 0.f;
        #pragma unroll
        for (int sl = 0; sl < KSPLIT; sl++) s += g_s1part[sl * (BSZ * NC) + idx];
        out[idx] = 2048.f * s + g_T[c];
    }
}

extern "C" void kernel_launch(void* const* d_in, const int* in_sizes, int n_in,
                              void* d_out, int out_size)
{
    const float* z1  = (const float*)d_in[0];
    const float* z2  = (const float*)d_in[1];
    const float* Wp  = (const float*)d_in[2];
    const float* bp  = (const float*)d_in[3];
    const float* Wfc = (const float*)d_in[4];
    const float* bfc = (const float*)d_in[5];
    float* out = (float*)d_out;

    cudaFuncSetAttribute(gemm1_tc, cudaFuncAttributeMaxDynamicSharedMemorySize, G1_SMEM);

    __nv_bfloat16* Bbf = nullptr;
    cudaGetSymbolAddress((void**)&Bbf, g_Bbf);

    // Side stream + events, created once (no device memory involved).
    static cudaStream_t s_side = nullptr;
    static cudaEvent_t  ev_fork = nullptr, ev_join = nullptr;
    if (s_side == nullptr) {
        cudaStreamCreateWithFlags(&s_side, cudaStreamNonBlocking);
        cudaEventCreateWithFlags(&ev_fork, cudaEventDisableTiming);
        cudaEventCreateWithFlags(&ev_join, cudaEventDisableTiming);
    }

    // Fork: side stream inherits capture via event wait.
    cudaEventRecord(ev_fork, 0);
    cudaStreamWaitEvent(s_side, ev_fork, 0);

    // Side branch: s1 (fp32, SIMT) — overlaps the compute-bound gemm chain.
    s1_kernel<<<dim3(16, KSPLIT), 256, 0, s_side>>>(z1, Wfc);
    cudaEventRecord(ev_join, s_side);

    // Main branch: convert B -> fused gemm1 (bf16 partials) -> relu+colsum -> s2
    convertB_kernel<<<592, 512>>>(Wp);
    gemm1_tc<<<128, 512, G1_SMEM>>>(z2, Bbf);
    relu_colsum_kernel<<<512, 256>>>(bp);
    s2_kernel<<<NC, 1024>>>(Wfc, bfc);

    // Join, then combine.
    cudaStreamWaitEvent(0, ev_join, 0);
    out_kernel<<<(BSZ * NC + 255) / 256, 256>>>(out);
}